// round 8
// baseline (speedup 1.0000x reference)
#include <cuda_runtime.h>
#include <cuda_fp16.h>
#include <math.h>

// ---------------------------------------------------------------------------
// GATNet: 4x GATConv + pool + MLP head -- ONE persistent kernel.
// 12 phases separated by software grid barriers.  Grid = 592 blocks
// (148 SMs x 4), __launch_bounds__(256,4) guarantees co-residency.
// Cross-phase global reads use __ldcg (L2) because L1 is NOT flushed
// between phases inside a single launch.
// ---------------------------------------------------------------------------

#define NNODES 20000
#define E0     320000
#define ETOT   (E0 + NNODES)
#define NG     8
#define NBLK   592
#define NTHR   256
#define GSTRIDE (NBLK * NTHR)

// Scratch (device globals; no allocations allowed)
__device__ __align__(16) float  g_featA[NNODES * 64];   // layer input (post-ELU), fp32
__device__ __align__(16) __half g_featT[NNODES * 64];   // transformed feats fp16 (L1-3)
__device__ __align__(16) __half g_ft4  [NNODES * 256];  // transformed feats fp16 (L4)
__device__ __align__(16) float  g_asrc [NNODES * 8];
__device__ __align__(16) float  g_adst [NNODES * 8];
__device__ float g_fp[NG * 64];
// CSR by destination. g_cnt zero on entry (static init call #1; re-zeroed in fill).
__device__ int g_cnt[NNODES];
__device__ int g_rowstart[NNODES + 1];
__device__ int g_cursor[NNODES];
__device__ int g_col[ETOT];
// Grid barrier state (generation counter; monotone across calls).
__device__ int g_barc;
__device__ int g_barg;

__device__ __forceinline__ float leaky02(float v) { return fmaxf(v, 0.2f * v); }
__device__ __forceinline__ float eluf(float v)    { return v > 0.f ? v : (__expf(v) - 1.f); }

// ---------------------------------------------------------------------------
// Software grid barrier with proper release/acquire fencing.
// ---------------------------------------------------------------------------
__device__ __forceinline__ void gbar() {
    __threadfence();              // release: every thread's stores visible
    __syncthreads();
    if (threadIdx.x == 0) {
        volatile int* vg = &g_barg;
        int gen = *vg;
        int arrived = atomicAdd(&g_barc, 1) + 1;
        if (arrived == NBLK) {
            g_barc = 0;
            __threadfence();
            atomicAdd(&g_barg, 1);
        } else {
            while (*vg == gen) { __nanosleep(64); }
        }
        __threadfence();          // acquire
    }
    __syncthreads();
}

// ---------------------------------------------------------------------------
// Phase: count in-degree
// ---------------------------------------------------------------------------
__device__ void ph_count(const int* __restrict__ ei, int gtid) {
    for (int e = gtid; e < ETOT; e += GSTRIDE) {
        int d = (e < E0) ? ei[E0 + e] : (e - E0);
        atomicAdd(&g_cnt[d], 1);
    }
}

// ---------------------------------------------------------------------------
// Phase: prefix scan (block 0); block 1 zeroes pool accumulator (ALL 512).
// ---------------------------------------------------------------------------
__device__ void ph_scan(int bid, int tid, int* sp) {
    if (bid == 1) {
        for (int i = tid; i < NG * 64; i += NTHR) g_fp[i] = 0.f;
        return;
    }
    if (bid != 0) return;
    const int CH = (NNODES + NTHR - 1) / NTHR;   // 79
    int b0 = tid * CH;
    int b1 = min(b0 + CH, NNODES);
    int sum = 0;
    for (int i = b0; i < b1; i++) sum += __ldcg(&g_cnt[i]);
    sp[tid] = sum;
    __syncthreads();
    for (int off = 1; off < NTHR; off <<= 1) {
        int v = (tid >= off) ? sp[tid - off] : 0;
        __syncthreads();
        sp[tid] += v;
        __syncthreads();
    }
    int base = (tid == 0) ? 0 : sp[tid - 1];
    for (int i = b0; i < b1; i++) {
        g_rowstart[i] = base;
        g_cursor[i]   = base;
        base += __ldcg(&g_cnt[i]);
    }
    if (tid == NTHR - 1) g_rowstart[NNODES] = base;
}

// ---------------------------------------------------------------------------
// Phase: fill CSR cols (and re-zero g_cnt for next call)
// ---------------------------------------------------------------------------
__device__ void ph_fill(const int* __restrict__ ei, int gtid) {
    for (int e = gtid; e < ETOT; e += GSTRIDE) {
        if (e < NNODES) g_cnt[e] = 0;
        int s, d;
        if (e < E0) { s = ei[e]; d = ei[E0 + e]; }
        else        { s = e - E0; d = e - E0; }
        int pos = atomicAdd(&g_cursor[d], 1);
        g_col[pos] = s;
    }
}

// ---------------------------------------------------------------------------
// Phase: node transform featT(half) = in @ W, logits asrc/adst (fp32).
// s_buf layout: sW[IN*D] | sx[NPB*IN] | sh[NPB*D]
// Feature input read via __ldcg when reading g_featA (cross-phase data).
// ---------------------------------------------------------------------------
template<int IN, int D, int H, int C, bool USE_G, bool STAGE_W>
__device__ void ph_transform(float* s_buf, int bid, int tid,
                             const float* __restrict__ xin,
                             const float* __restrict__ W,
                             const float* __restrict__ a_src,
                             const float* __restrict__ a_dst) {
    constexpr int QUADS = D / 4;
    constexpr int NPB   = NTHR / QUADS;        // 16 (D=64) or 4 (D=256)
    float* sW = s_buf;
    float* sx = s_buf + (STAGE_W ? IN * D : 0);
    float* sh = sx + NPB * IN;

    const int li = tid / QUADS;
    const int q  = tid % QUADS;
    __half* __restrict__ fout = (D == 256) ? g_ft4 : g_featT;

    if (STAGE_W) {
        for (int i = tid; i < IN * D / 4; i += NTHR)
            ((float4*)sW)[i] = ((const float4*)W)[i];
    }

    const int ntiles = (NNODES + NPB - 1) / NPB;
    for (int tile = bid; tile < ntiles; tile += NBLK) {
        __syncthreads();
        for (int i = tid; i < NPB * IN; i += NTHR) {
            int nn = tile * NPB + i / IN;
            float v = 0.f;
            if (nn < NNODES) {
                v = USE_G ? __ldcg(&g_featA[nn * IN + i % IN])
                          : xin[nn * IN + i % IN];
            }
            sx[(i / IN) * IN + (i % IN)] = v;
        }
        __syncthreads();

        const int n = tile * NPB + li;
        float4 acc = make_float4(0.f, 0.f, 0.f, 0.f);
#pragma unroll
        for (int i = 0; i < IN; i++) {
            float xv = sx[li * IN + i];
            float4 w4 = STAGE_W ? *(const float4*)&sW[i * D + 4 * q]
                                : __ldg((const float4*)&W[i * D + 4 * q]);
            acc.x += xv * w4.x; acc.y += xv * w4.y;
            acc.z += xv * w4.z; acc.w += xv * w4.w;
        }
        if (n < NNODES) {
            __half2* dst = (__half2*)&fout[n * D + 4 * q];
            dst[0] = __floats2half2_rn(acc.x, acc.y);
            dst[1] = __floats2half2_rn(acc.z, acc.w);
            *(float4*)&sh[li * D + 4 * q] = acc;
        }
        __syncthreads();

        if (tid < NPB * H) {
            int ln = tid / H, h = tid % H;
            int nn = tile * NPB + ln;
            if (nn < NNODES) {
                float as = 0.f, ad = 0.f;
#pragma unroll
                for (int c = 0; c < C; c++) {
                    float hv = sh[ln * D + h * C + c];
                    as += hv * a_src[h * C + c];
                    ad += hv * a_dst[h * C + c];
                }
                g_asrc[nn * H + h] = as;
                g_adst[nn * H + h] = ad;
            }
        }
    }
}

// ---------------------------------------------------------------------------
// Phase: aggregation, concat layers (H=8,C=8,D=64).  Warp per node,
// grid-strided.  Lane owns channel pair (2L,2L+1), head L>>2.
// All gathers via __ldcg (cross-phase data; L1 may be stale).
// ---------------------------------------------------------------------------
__device__ void ph_agg8(const float* __restrict__ bias, int gwarp, int lane) {
    const __half2* __restrict__ ft = (const __half2*)g_featT;
    const int h = lane >> 2;
    const float bx = bias[2 * lane];
    const float by = bias[2 * lane + 1];
    for (int d = gwarp; d < NNODES; d += NBLK * 8) {
        const float adv = __ldcg(&g_adst[d * 8 + h]);
        const int r0 = __ldcg(&g_rowstart[d]);
        const int r1 = __ldcg(&g_rowstart[d + 1]);
        float den = 0.f, ax = 0.f, ay = 0.f;
#pragma unroll 4
        for (int j = r0; j < r1; j++) {
            int s = __ldcg(&g_col[j]);
            float e = __expf(leaky02(__ldcg(&g_asrc[s * 8 + h]) + adv));
            den += e;
            float2 f = __half22float2(__ldcg(&ft[s * 32 + lane]));
            ax += e * f.x;
            ay += e * f.y;
        }
        float inv = 1.f / den;
        float2 o;
        o.x = eluf(ax * inv + bx);
        o.y = eluf(ay * inv + by);
        *(float2*)&g_featA[d * 64 + 2 * lane] = o;
    }
}

// ---------------------------------------------------------------------------
// Phase: aggregation, layer 4 (H=4, C=64, mean over heads).  Warp per node.
// ---------------------------------------------------------------------------
__device__ void ph_agg4(const float* __restrict__ bias, int gwarp, int lane) {
    const __half2* __restrict__ ft = (const __half2*)g_ft4;
    const float bx = bias[2 * lane];
    const float by = bias[2 * lane + 1];
    for (int d = gwarp; d < NNODES; d += NBLK * 8) {
        const float4 adv = __ldcg((const float4*)&g_adst[d * 4]);
        const int r0 = __ldcg(&g_rowstart[d]);
        const int r1 = __ldcg(&g_rowstart[d + 1]);
        float den[4] = {0.f, 0.f, 0.f, 0.f};
        float ax[4]  = {0.f, 0.f, 0.f, 0.f};
        float ay[4]  = {0.f, 0.f, 0.f, 0.f};
#pragma unroll 2
        for (int j = r0; j < r1; j++) {
            int s = __ldcg(&g_col[j]);
            float4 as4 = __ldcg((const float4*)&g_asrc[s * 4]);
            float ev[4];
            ev[0] = __expf(leaky02(as4.x + adv.x));
            ev[1] = __expf(leaky02(as4.y + adv.y));
            ev[2] = __expf(leaky02(as4.z + adv.z));
            ev[3] = __expf(leaky02(as4.w + adv.w));
#pragma unroll
            for (int hh = 0; hh < 4; hh++) {
                float2 f = __half22float2(__ldcg(&ft[s * 128 + hh * 32 + lane]));
                den[hh] += ev[hh];
                ax[hh]  += ev[hh] * f.x;
                ay[hh]  += ev[hh] * f.y;
            }
        }
        float v1 = 0.f, v2 = 0.f;
#pragma unroll
        for (int hh = 0; hh < 4; hh++) {
            float inv = 1.f / den[hh];
            v1 += ax[hh] * inv;
            v2 += ay[hh] * inv;
        }
        float2 o;
        o.x = eluf(0.25f * v1 + bx);
        o.y = eluf(0.25f * v2 + by);
        *(float2*)&g_featA[d * 64 + 2 * lane] = o;
    }
}

// ---------------------------------------------------------------------------
// Phase: pooling over function nodes (flag sorted).  Blocks 0..31.
// ---------------------------------------------------------------------------
__device__ void ph_pool(const int* __restrict__ fidx, const int* __restrict__ flag,
                        int nf, int bid, int tid) {
    if (bid >= 32) return;
    int c   = tid & 63;
    int row = tid >> 6;
    int per = (nf + 31) / 32;
    int i0  = bid * per;
    int i1  = min(i0 + per, nf);
    float acc = 0.f;
    int cur = -1;
    for (int i = i0 + row; i < i1; i += 4) {
        int g = flag[i];
        float v = __ldcg(&g_featA[fidx[i] * 64 + c]);
        if (g != cur) {
            if (cur >= 0) atomicAdd(&g_fp[cur * 64 + c], acc);
            cur = g; acc = 0.f;
        }
        acc += v;
    }
    if (cur >= 0) atomicAdd(&g_fp[cur * 64 + c], acc);
}

// ---------------------------------------------------------------------------
// Phase: head (block 0 only).
// s_buf layout: sfp[64] | stg[64] | red[128]
// ---------------------------------------------------------------------------
__device__ void ph_head(float* s_buf, int bid, int tid,
                        const int* __restrict__ dvi,
                        const float* __restrict__ Wp,
                        const float* __restrict__ Wt,
                        const float* __restrict__ Wo,
                        const float* __restrict__ bo,
                        float* __restrict__ out) {
    if (bid != 0) return;
    float* sfp = s_buf;
    float* stg = s_buf + 64;
    float* red = s_buf + 128;
    for (int g = 0; g < NG; g++) {
        if (tid < 64) {
            sfp[tid] = __ldcg(&g_fp[g * 64 + tid]);
            stg[tid] = __ldcg(&g_featA[dvi[g] * 64 + tid]);
        }
        __syncthreads();
        if (tid < 128) {
            float acc = 0.f;
            if (tid < 64) {
#pragma unroll
                for (int k = 0; k < 64; k++) acc += sfp[k] * Wp[k * 64 + tid];
            } else {
                int c = tid - 64;
#pragma unroll
                for (int k = 0; k < 64; k++) acc += stg[k] * Wt[k * 64 + c];
            }
            red[tid] = eluf(acc) * Wo[tid];
        }
        __syncthreads();
        for (int s2 = 64; s2 > 0; s2 >>= 1) {
            if (tid < s2) red[tid] += red[tid + s2];
            __syncthreads();
        }
        if (tid == 0) out[g] = red[0] + bo[0];
        __syncthreads();
    }
}

// ---------------------------------------------------------------------------
// The persistent mega-kernel.
// ---------------------------------------------------------------------------
__global__ void __launch_bounds__(NTHR, 4)
k_gatnet(const float* __restrict__ x,   const int* __restrict__ ei,
         const int* __restrict__ fidx,  const int* __restrict__ flag,
         const int* __restrict__ dvi,
         const float* __restrict__ W1, const float* __restrict__ as1,
         const float* __restrict__ ad1, const float* __restrict__ b1,
         const float* __restrict__ W2, const float* __restrict__ as2,
         const float* __restrict__ ad2, const float* __restrict__ b2,
         const float* __restrict__ W3, const float* __restrict__ as3,
         const float* __restrict__ ad3, const float* __restrict__ b3,
         const float* __restrict__ W4, const float* __restrict__ as4,
         const float* __restrict__ ad4, const float* __restrict__ b4,
         const float* __restrict__ Wp, const float* __restrict__ Wt,
         const float* __restrict__ Wo, const float* __restrict__ bo,
         float* __restrict__ out, int nf) {
    __shared__ __align__(16) float s_buf[6144];   // 24 KB

    const int bid   = blockIdx.x;
    const int tid   = threadIdx.x;
    const int gtid  = bid * NTHR + tid;
    const int lane  = tid & 31;
    const int gwarp = gtid >> 5;

    // ---- CSR build ----
    ph_count(ei, gtid);
    gbar();
    ph_scan(bid, tid, (int*)s_buf);
    gbar();
    ph_fill(ei, gtid);
    gbar();

    // ---- Layer 1: 16 -> 8x8 concat ----
    ph_transform<16, 64, 8, 8, false, true>(s_buf, bid, tid, x, W1, as1, ad1);
    gbar();
    ph_agg8(b1, gwarp, lane);
    gbar();
    // ---- Layer 2 ----
    ph_transform<64, 64, 8, 8, true, true>(s_buf, bid, tid, nullptr, W2, as2, ad2);
    gbar();
    ph_agg8(b2, gwarp, lane);
    gbar();
    // ---- Layer 3 ----
    ph_transform<64, 64, 8, 8, true, true>(s_buf, bid, tid, nullptr, W3, as3, ad3);
    gbar();
    ph_agg8(b3, gwarp, lane);
    gbar();
    // ---- Layer 4: 64 -> 4 heads x 64, mean ----
    ph_transform<64, 256, 4, 64, true, false>(s_buf, bid, tid, nullptr, W4, as4, ad4);
    gbar();
    ph_agg4(b4, gwarp, lane);
    gbar();

    // ---- Pool + head ----
    ph_pool(fidx, flag, nf, bid, tid);
    gbar();
    ph_head(s_buf, bid, tid, dvi, Wp, Wt, Wo, bo, out);
}

// ---------------------------------------------------------------------------
extern "C" void kernel_launch(void* const* d_in, const int* in_sizes, int n_in,
                              void* d_out, int out_size) {
    const float* x     = (const float*)d_in[0];
    const int*   ei    = (const int*)  d_in[1];
    const int*   fidx  = (const int*)  d_in[2];
    const int*   flag  = (const int*)  d_in[3];
    const int*   dvi   = (const int*)  d_in[4];

    k_gatnet<<<NBLK, NTHR>>>(
        x, ei, fidx, flag, dvi,
        (const float*)d_in[5],  (const float*)d_in[6],  (const float*)d_in[7],  (const float*)d_in[8],
        (const float*)d_in[9],  (const float*)d_in[10], (const float*)d_in[11], (const float*)d_in[12],
        (const float*)d_in[13], (const float*)d_in[14], (const float*)d_in[15], (const float*)d_in[16],
        (const float*)d_in[17], (const float*)d_in[18], (const float*)d_in[19], (const float*)d_in[20],
        (const float*)d_in[21], (const float*)d_in[22], (const float*)d_in[23], (const float*)d_in[24],
        (float*)d_out, in_sizes[2]);
}

// round 10
// speedup vs baseline: 1.4206x; 1.4206x over previous
#include <cuda_runtime.h>
#include <cuda_fp16.h>
#include <math.h>

// ---------------------------------------------------------------------------
// GATNet: 4x GATConv + pool + MLP head.  Multi-kernel, CSR-by-dst,
// single-pass softmax, fp16 feature gathers.
// R10 = R9 with the k_transform4 interleaved-store pair index fixed:
// pair must be LOCAL within the head ((2q)&31), not global 2q.
// ---------------------------------------------------------------------------

#define NNODES 20000
#define E0     320000
#define ETOT   (E0 + NNODES)
#define NG     8
#define SCAN_T 1024
#define SCAN_CHUNK ((NNODES + SCAN_T - 1) / SCAN_T)

// Scratch (device globals; no allocations allowed)
__device__ __align__(16) float  g_featA[NNODES * 64];   // layer input (post-ELU) fp32
__device__ __align__(16) __half g_featT[NNODES * 64];   // L1-3 transformed feats fp16
__device__ __align__(16) __half g_ft4  [NNODES * 256];  // L4 feats fp16, [pair32][head4] half2
__device__ __align__(16) float  g_asrc [NNODES * 8];
__device__ __align__(16) float  g_adst [NNODES * 8];
__device__ float g_fp[NG * 64];
// CSR by destination. g_cnt zero on entry (static init; re-zeroed in k_fill).
__device__ int g_cnt[NNODES];
__device__ int g_rowstart[NNODES + 1];
__device__ int g_cursor[NNODES];
__device__ int g_col[ETOT];

__device__ __forceinline__ float leaky02(float v) { return fmaxf(v, 0.2f * v); }
__device__ __forceinline__ float eluf(float v)    { return v > 0.f ? v : (__expf(v) - 1.f); }

// ---------------------------------------------------------------------------
// CSR build
// ---------------------------------------------------------------------------
__global__ void k_count(const int* __restrict__ ei) {
    int e = blockIdx.x * blockDim.x + threadIdx.x;
    if (e >= ETOT) return;
    int d = (e < E0) ? ei[E0 + e] : (e - E0);
    atomicAdd(&g_cnt[d], 1);
}
__global__ void k_scan() {
    __shared__ int sp[SCAN_T];
    int t = threadIdx.x;
    if (t < NG * 64) g_fp[t] = 0.f;          // zero pool accumulator
    int b0 = t * SCAN_CHUNK;
    int b1 = min(b0 + SCAN_CHUNK, NNODES);
    int sum = 0;
    for (int i = b0; i < b1; i++) sum += g_cnt[i];
    sp[t] = sum;
    __syncthreads();
    for (int off = 1; off < SCAN_T; off <<= 1) {
        int v = (t >= off) ? sp[t - off] : 0;
        __syncthreads();
        sp[t] += v;
        __syncthreads();
    }
    int base = (t == 0) ? 0 : sp[t - 1];
    for (int i = b0; i < b1; i++) {
        g_rowstart[i] = base;
        g_cursor[i]   = base;
        base += g_cnt[i];
    }
    if (t == SCAN_T - 1) g_rowstart[NNODES] = base;
}
__global__ void k_fill(const int* __restrict__ ei) {
    int e = blockIdx.x * blockDim.x + threadIdx.x;
    if (e < NNODES) g_cnt[e] = 0;            // self-clean for next call
    if (e >= ETOT) return;
    int s, d;
    if (e < E0) { s = ei[e]; d = ei[E0 + e]; }
    else        { s = e - E0; d = e - E0; }
    int pos = atomicAdd(&g_cursor[d], 1);
    g_col[pos] = s;
}

// ---------------------------------------------------------------------------
// Transform for layers 1-3 (D=64).  16 nodes/block-tile, W staged in smem.
// ---------------------------------------------------------------------------
template<int IN, bool USE_G>
__global__ void k_transform64(const float* __restrict__ xin,
                              const float* __restrict__ W,
                              const float* __restrict__ a_src,
                              const float* __restrict__ a_dst) {
    constexpr int D = 64, H = 8, C = 8, NPB = 16;
    __shared__ __align__(16) float sW[IN * D];
    __shared__ __align__(16) float sx[NPB][IN];
    __shared__ __align__(16) float sh[NPB][D];
    const int t  = threadIdx.x;
    const int li = t / 16;
    const int q  = t % 16;
    const float* __restrict__ xp = USE_G ? (const float*)g_featA : xin;

    for (int i = t; i < IN * D / 4; i += 256)
        ((float4*)sW)[i] = ((const float4*)W)[i];

    const int ntiles = NNODES / NPB;           // 1250
    for (int tile = blockIdx.x; tile < ntiles; tile += gridDim.x) {
        __syncthreads();
        for (int i = t; i < NPB * IN; i += 256) {
            int nn = tile * NPB + i / IN;
            sx[i / IN][i % IN] = xp[nn * IN + i % IN];
        }
        __syncthreads();

        const int n = tile * NPB + li;
        float4 acc = make_float4(0.f, 0.f, 0.f, 0.f);
#pragma unroll
        for (int i = 0; i < IN; i++) {
            float xv = sx[li][i];
            float4 w4 = *(const float4*)&sW[i * D + 4 * q];
            acc.x += xv * w4.x; acc.y += xv * w4.y;
            acc.z += xv * w4.z; acc.w += xv * w4.w;
        }
        {
            __half2* dst = (__half2*)&g_featT[n * D + 4 * q];
            dst[0] = __floats2half2_rn(acc.x, acc.y);
            dst[1] = __floats2half2_rn(acc.z, acc.w);
            *(float4*)&sh[li][4 * q] = acc;
        }
        __syncthreads();

        if (t < NPB * H) {
            int ln = t / H, h = t % H;
            int nn = tile * NPB + ln;
            float as = 0.f, ad = 0.f;
#pragma unroll
            for (int c = 0; c < C; c++) {
                float hv = sh[ln][h * C + c];
                as += hv * a_src[h * C + c];
                ad += hv * a_dst[h * C + c];
            }
            g_asrc[nn * H + h] = as;
            g_adst[nn * H + h] = ad;
        }
    }
}

// ---------------------------------------------------------------------------
// Layer-4 transform (64 -> 256): 16 nodes/tile, 4 nodes per thread.
// Thread t: q = t&63 (out quad of 256 channels), m = t>>6 -> nodes 4m..4m+3.
// W4 float4 fetched ONCE per 4 nodes.  Output stored head-interleaved:
// f4[n*128 + pair*4 + head], pair = LOCAL channel pair within head ((2q)&31).
// ---------------------------------------------------------------------------
__global__ void k_transform4(const float* __restrict__ W,
                             const float* __restrict__ a_src,
                             const float* __restrict__ a_dst) {
    constexpr int NPB = 16;
    __shared__ __align__(16) float sx[NPB][64];    // 4 KB
    __shared__ __align__(16) float sh[NPB][256];   // 16 KB
    const int t = threadIdx.x;
    const int q = t & 63;
    const int m = t >> 6;
    const int h  = q >> 4;                         // head of channels 4q..4q+3
    const int p0 = (2 * q) & 31;                   // local pair of channel 4q
    __half2* __restrict__ f4 = (__half2*)g_ft4;

    const int ntiles = NNODES / NPB;               // 1250
    for (int tile = blockIdx.x; tile < ntiles; tile += gridDim.x) {
        __syncthreads();
        for (int i = t; i < NPB * 64; i += 256) {
            int nn = tile * NPB + (i >> 6);
            sx[i >> 6][i & 63] = g_featA[nn * 64 + (i & 63)];
        }
        __syncthreads();

        float4 acc0 = make_float4(0.f,0.f,0.f,0.f);
        float4 acc1 = make_float4(0.f,0.f,0.f,0.f);
        float4 acc2 = make_float4(0.f,0.f,0.f,0.f);
        float4 acc3 = make_float4(0.f,0.f,0.f,0.f);
#pragma unroll 4
        for (int k = 0; k < 64; k++) {
            float4 w4 = __ldg((const float4*)&W[k * 256 + 4 * q]);
            float x0 = sx[m * 4 + 0][k];
            float x1 = sx[m * 4 + 1][k];
            float x2 = sx[m * 4 + 2][k];
            float x3 = sx[m * 4 + 3][k];
            acc0.x += x0*w4.x; acc0.y += x0*w4.y; acc0.z += x0*w4.z; acc0.w += x0*w4.w;
            acc1.x += x1*w4.x; acc1.y += x1*w4.y; acc1.z += x1*w4.z; acc1.w += x1*w4.w;
            acc2.x += x2*w4.x; acc2.y += x2*w4.y; acc2.z += x2*w4.z; acc2.w += x2*w4.w;
            acc3.x += x3*w4.x; acc3.y += x3*w4.y; acc3.z += x3*w4.z; acc3.w += x3*w4.w;
        }
        float4 accs[4] = {acc0, acc1, acc2, acc3};
#pragma unroll
        for (int i = 0; i < 4; i++) {
            int nl = m * 4 + i;
            int n  = tile * NPB + nl;
            f4[n * 128 + p0 * 4 + h]       = __floats2half2_rn(accs[i].x, accs[i].y);
            f4[n * 128 + (p0 + 1) * 4 + h] = __floats2half2_rn(accs[i].z, accs[i].w);
            *(float4*)&sh[nl][4 * q] = accs[i];
        }
        __syncthreads();

        if (t < NPB * 4) {                         // 16 nodes x 4 heads
            int nl = t >> 2, hh = t & 3;
            int nn = tile * NPB + nl;
            float as = 0.f, ad = 0.f;
#pragma unroll 8
            for (int c = 0; c < 64; c++) {
                float hv = sh[nl][hh * 64 + c];
                as += hv * a_src[hh * 64 + c];
                ad += hv * a_dst[hh * 64 + c];
            }
            g_asrc[nn * 4 + hh] = as;
            g_adst[nn * 4 + hh] = ad;
        }
    }
}

// ---------------------------------------------------------------------------
// Aggregation, concat layers (H=8,C=8,D=64): TWO nodes per warp.
// Lanes 0-15 -> node 2*wid, lanes 16-31 -> node 2*wid+1.
// Lane sl (=lane&15) owns channels 4sl..4sl+3 (head sl>>1), one 8B gather.
// ---------------------------------------------------------------------------
__global__ void k_agg8(const float* __restrict__ bias) {
    int wid  = (blockIdx.x * blockDim.x + threadIdx.x) >> 5;
    int lane = threadIdx.x & 31;
    if (wid >= NNODES / 2) return;
    const int sl = lane & 15;
    const int d  = 2 * wid + (lane >> 4);
    const int h  = sl >> 1;
    const float adv = g_adst[d * 8 + h];
    const int r0 = g_rowstart[d];
    const int r1 = g_rowstart[d + 1];
    const uint2* __restrict__ ftp = (const uint2*)g_featT;   // 8B = 4 halves

    float den = 0.f;
    float a0 = 0.f, a1 = 0.f, a2 = 0.f, a3 = 0.f;
#pragma unroll 4
    for (int j = r0; j < r1; j++) {
        int s = g_col[j];
        float e = __expf(leaky02(g_asrc[s * 8 + h] + adv));
        den += e;
        uint2 raw = __ldg(&ftp[s * 16 + sl]);
        float2 lo = __half22float2(*(const __half2*)&raw.x);
        float2 hi = __half22float2(*(const __half2*)&raw.y);
        a0 += e * lo.x; a1 += e * lo.y;
        a2 += e * hi.x; a3 += e * hi.y;
    }
    float inv = 1.f / den;
    float4 b = *(const float4*)&bias[4 * sl];
    float4 o;
    o.x = eluf(a0 * inv + b.x);
    o.y = eluf(a1 * inv + b.y);
    o.z = eluf(a2 * inv + b.z);
    o.w = eluf(a3 * inv + b.w);
    *(float4*)&g_featA[d * 64 + 4 * sl] = o;
}

// ---------------------------------------------------------------------------
// Aggregation, layer 4 (H=4, C=64, mean over heads).  Warp per node.
// Lane owns channel pair (2L,2L+1); ONE 16B gather gives all 4 heads.
// ---------------------------------------------------------------------------
__global__ void k_agg4(const float* __restrict__ bias) {
    int wid  = (blockIdx.x * blockDim.x + threadIdx.x) >> 5;
    int lane = threadIdx.x & 31;
    if (wid >= NNODES) return;
    const int d = wid;
    const float4 adv = *(const float4*)&g_adst[d * 4];
    const int r0 = g_rowstart[d];
    const int r1 = g_rowstart[d + 1];
    const uint4* __restrict__ ftp = (const uint4*)g_ft4;   // 16B = pair x 4 heads

    float den[4] = {0.f, 0.f, 0.f, 0.f};
    float ax[4]  = {0.f, 0.f, 0.f, 0.f};
    float ay[4]  = {0.f, 0.f, 0.f, 0.f};
#pragma unroll 4
    for (int j = r0; j < r1; j++) {
        int s = g_col[j];
        float4 as4 = *(const float4*)&g_asrc[s * 4];
        uint4 raw = __ldg(&ftp[s * 32 + lane]);
        float ev[4];
        ev[0] = __expf(leaky02(as4.x + adv.x));
        ev[1] = __expf(leaky02(as4.y + adv.y));
        ev[2] = __expf(leaky02(as4.z + adv.z));
        ev[3] = __expf(leaky02(as4.w + adv.w));
        float2 f0 = __half22float2(*(const __half2*)&raw.x);
        float2 f1 = __half22float2(*(const __half2*)&raw.y);
        float2 f2 = __half22float2(*(const __half2*)&raw.z);
        float2 f3 = __half22float2(*(const __half2*)&raw.w);
        den[0] += ev[0]; ax[0] += ev[0] * f0.x; ay[0] += ev[0] * f0.y;
        den[1] += ev[1]; ax[1] += ev[1] * f1.x; ay[1] += ev[1] * f1.y;
        den[2] += ev[2]; ax[2] += ev[2] * f2.x; ay[2] += ev[2] * f2.y;
        den[3] += ev[3]; ax[3] += ev[3] * f3.x; ay[3] += ev[3] * f3.y;
    }
    float v1 = 0.f, v2 = 0.f;
#pragma unroll
    for (int hh = 0; hh < 4; hh++) {
        float inv = 1.f / den[hh];
        v1 += ax[hh] * inv;
        v2 += ay[hh] * inv;
    }
    float2 b = *(const float2*)&bias[2 * lane];
    float2 o;
    o.x = eluf(0.25f * v1 + b.x);
    o.y = eluf(0.25f * v2 + b.y);
    *(float2*)&g_featA[d * 64 + 2 * lane] = o;
}

// ---------------------------------------------------------------------------
// Pooling (flag sorted): register run-accumulation, few atomics.
// ---------------------------------------------------------------------------
__global__ void k_pool(const int* __restrict__ fidx, const int* __restrict__ flag, int nf) {
    int c   = threadIdx.x & 63;
    int row = threadIdx.x >> 6;
    int per = (nf + gridDim.x - 1) / gridDim.x;
    int i0  = blockIdx.x * per;
    int i1  = min(i0 + per, nf);
    float acc = 0.f;
    int cur = -1;
    for (int i = i0 + row; i < i1; i += 4) {
        int g = flag[i];
        float v = g_featA[fidx[i] * 64 + c];
        if (g != cur) {
            if (cur >= 0) atomicAdd(&g_fp[cur * 64 + c], acc);
            cur = g; acc = 0.f;
        }
        acc += v;
    }
    if (cur >= 0) atomicAdd(&g_fp[cur * 64 + c], acc);
}

// ---------------------------------------------------------------------------
// Head: z = elu([fp@Wp, h4[dvi]@Wt]); out = z@Wo + bo
// ---------------------------------------------------------------------------
__global__ void k_head(const int* __restrict__ dvi,
                       const float* __restrict__ Wp,
                       const float* __restrict__ Wt,
                       const float* __restrict__ Wo,
                       const float* __restrict__ bo,
                       float* __restrict__ out) {
    __shared__ float sfp[64], stg[64], red[128];
    int g = blockIdx.x, t = threadIdx.x;
    if (t < 64) {
        sfp[t] = g_fp[g * 64 + t];
        stg[t] = g_featA[dvi[g] * 64 + t];
    }
    __syncthreads();
    float acc = 0.f;
    if (t < 64) {
#pragma unroll
        for (int k = 0; k < 64; k++) acc += sfp[k] * Wp[k * 64 + t];
    } else {
        int c = t - 64;
#pragma unroll
        for (int k = 0; k < 64; k++) acc += stg[k] * Wt[k * 64 + c];
    }
    red[t] = eluf(acc) * Wo[t];
    __syncthreads();
    for (int s2 = 64; s2 > 0; s2 >>= 1) {
        if (t < s2) red[t] += red[t + s2];
        __syncthreads();
    }
    if (t == 0) out[g] = red[0] + bo[0];
}

// ---------------------------------------------------------------------------
extern "C" void kernel_launch(void* const* d_in, const int* in_sizes, int n_in,
                              void* d_out, int out_size) {
    const float* x     = (const float*)d_in[0];
    const int*   ei    = (const int*)  d_in[1];
    const int*   fidx  = (const int*)  d_in[2];
    const int*   flag  = (const int*)  d_in[3];
    const int*   dvi   = (const int*)  d_in[4];
    const float* W1    = (const float*)d_in[5];
    const float* as1   = (const float*)d_in[6];
    const float* ad1   = (const float*)d_in[7];
    const float* b1    = (const float*)d_in[8];
    const float* W2    = (const float*)d_in[9];
    const float* as2   = (const float*)d_in[10];
    const float* ad2   = (const float*)d_in[11];
    const float* b2    = (const float*)d_in[12];
    const float* W3    = (const float*)d_in[13];
    const float* as3   = (const float*)d_in[14];
    const float* ad3   = (const float*)d_in[15];
    const float* b3    = (const float*)d_in[16];
    const float* W4    = (const float*)d_in[17];
    const float* as4   = (const float*)d_in[18];
    const float* ad4   = (const float*)d_in[19];
    const float* b4    = (const float*)d_in[20];
    const float* Wp    = (const float*)d_in[21];
    const float* Wt    = (const float*)d_in[22];
    const float* Wo    = (const float*)d_in[23];
    const float* bo    = (const float*)d_in[24];
    float* out = (float*)d_out;

    const int nf  = in_sizes[2];                 // 8000
    const int EB  = (ETOT + 255) / 256;
    const int AB8 = (NNODES / 2 * 32 + 255) / 256;   // 2 nodes/warp
    const int AB4 = (NNODES * 32 + 255) / 256;

    // ---- CSR build ----
    k_count<<<EB, 256>>>(ei);
    k_scan<<<1, SCAN_T>>>();
    k_fill<<<EB, 256>>>(ei);

    // ---- Layer 1: 16 -> 8x8 concat ----
    k_transform64<16, false><<<625, 256>>>(x, W1, as1, ad1);
    k_agg8<<<AB8, 256>>>(b1);
    // ---- Layer 2 ----
    k_transform64<64, true><<<625, 256>>>(nullptr, W2, as2, ad2);
    k_agg8<<<AB8, 256>>>(b2);
    // ---- Layer 3 ----
    k_transform64<64, true><<<625, 256>>>(nullptr, W3, as3, ad3);
    k_agg8<<<AB8, 256>>>(b3);
    // ---- Layer 4: 64 -> 4 heads x 64, mean ----
    k_transform4<<<1250, 256>>>(W4, as4, ad4);
    k_agg4<<<AB4, 256>>>(b4);

    // ---- Pool + head ----
    k_pool<<<32, 256>>>(fidx, flag, nf);
    k_head<<<NG, 128>>>(dvi, Wp, Wt, Wo, bo, out);
}

// round 11
// speedup vs baseline: 1.4379x; 1.0121x over previous
#include <cuda_runtime.h>
#include <cuda_fp16.h>
#include <math.h>

// ---------------------------------------------------------------------------
// GATNet: 4x GATConv + pool + MLP head.  Multi-kernel, CSR-by-dst,
// single-pass softmax, fp16 feature gathers.
// R11: agg8 with 4 nodes/warp (lane = node x head, zero exp duplication);
// agg4 with shfl-broadcast exp (1 MUFU per edge-head instead of 32).
// ---------------------------------------------------------------------------

#define NNODES 20000
#define E0     320000
#define ETOT   (E0 + NNODES)
#define NG     8
#define SCAN_T 1024
#define SCAN_CHUNK ((NNODES + SCAN_T - 1) / SCAN_T)

// Scratch (device globals; no allocations allowed)
__device__ __align__(16) float  g_featA[NNODES * 64];   // layer input (post-ELU) fp32
__device__ __align__(16) __half g_featT[NNODES * 64];   // L1-3 transformed feats fp16
__device__ __align__(16) __half g_ft4  [NNODES * 256];  // L4 feats fp16, [pair32][head4] half2
__device__ __align__(16) float  g_asrc [NNODES * 8];
__device__ __align__(16) float  g_adst [NNODES * 8];
__device__ float g_fp[NG * 64];
// CSR by destination. g_cnt zero on entry (static init; re-zeroed in k_fill).
__device__ int g_cnt[NNODES];
__device__ int g_rowstart[NNODES + 1];
__device__ int g_cursor[NNODES];
__device__ int g_col[ETOT];

__device__ __forceinline__ float leaky02(float v) { return fmaxf(v, 0.2f * v); }
__device__ __forceinline__ float eluf(float v)    { return v > 0.f ? v : (__expf(v) - 1.f); }

// ---------------------------------------------------------------------------
// CSR build
// ---------------------------------------------------------------------------
__global__ void k_count(const int* __restrict__ ei) {
    int e = blockIdx.x * blockDim.x + threadIdx.x;
    if (e >= ETOT) return;
    int d = (e < E0) ? ei[E0 + e] : (e - E0);
    atomicAdd(&g_cnt[d], 1);
}
__global__ void k_scan() {
    __shared__ int sp[SCAN_T];
    int t = threadIdx.x;
    if (t < NG * 64) g_fp[t] = 0.f;          // zero pool accumulator
    int b0 = t * SCAN_CHUNK;
    int b1 = min(b0 + SCAN_CHUNK, NNODES);
    int sum = 0;
    for (int i = b0; i < b1; i++) sum += g_cnt[i];
    sp[t] = sum;
    __syncthreads();
    for (int off = 1; off < SCAN_T; off <<= 1) {
        int v = (t >= off) ? sp[t - off] : 0;
        __syncthreads();
        sp[t] += v;
        __syncthreads();
    }
    int base = (t == 0) ? 0 : sp[t - 1];
    for (int i = b0; i < b1; i++) {
        g_rowstart[i] = base;
        g_cursor[i]   = base;
        base += g_cnt[i];
    }
    if (t == SCAN_T - 1) g_rowstart[NNODES] = base;
}
__global__ void k_fill(const int* __restrict__ ei) {
    int e = blockIdx.x * blockDim.x + threadIdx.x;
    if (e < NNODES) g_cnt[e] = 0;            // self-clean for next call
    if (e >= ETOT) return;
    int s, d;
    if (e < E0) { s = ei[e]; d = ei[E0 + e]; }
    else        { s = e - E0; d = e - E0; }
    int pos = atomicAdd(&g_cursor[d], 1);
    g_col[pos] = s;
}

// ---------------------------------------------------------------------------
// Transform for layers 1-3 (D=64).  16 nodes/block-tile, W staged in smem.
// ---------------------------------------------------------------------------
template<int IN, bool USE_G>
__global__ void k_transform64(const float* __restrict__ xin,
                              const float* __restrict__ W,
                              const float* __restrict__ a_src,
                              const float* __restrict__ a_dst) {
    constexpr int D = 64, H = 8, C = 8, NPB = 16;
    __shared__ __align__(16) float sW[IN * D];
    __shared__ __align__(16) float sx[NPB][IN];
    __shared__ __align__(16) float sh[NPB][D];
    const int t  = threadIdx.x;
    const int li = t / 16;
    const int q  = t % 16;
    const float* __restrict__ xp = USE_G ? (const float*)g_featA : xin;

    for (int i = t; i < IN * D / 4; i += 256)
        ((float4*)sW)[i] = ((const float4*)W)[i];

    const int ntiles = NNODES / NPB;           // 1250
    for (int tile = blockIdx.x; tile < ntiles; tile += gridDim.x) {
        __syncthreads();
        for (int i = t; i < NPB * IN; i += 256) {
            int nn = tile * NPB + i / IN;
            sx[i / IN][i % IN] = xp[nn * IN + i % IN];
        }
        __syncthreads();

        const int n = tile * NPB + li;
        float4 acc = make_float4(0.f, 0.f, 0.f, 0.f);
#pragma unroll
        for (int i = 0; i < IN; i++) {
            float xv = sx[li][i];
            float4 w4 = *(const float4*)&sW[i * D + 4 * q];
            acc.x += xv * w4.x; acc.y += xv * w4.y;
            acc.z += xv * w4.z; acc.w += xv * w4.w;
        }
        {
            __half2* dst = (__half2*)&g_featT[n * D + 4 * q];
            dst[0] = __floats2half2_rn(acc.x, acc.y);
            dst[1] = __floats2half2_rn(acc.z, acc.w);
            *(float4*)&sh[li][4 * q] = acc;
        }
        __syncthreads();

        if (t < NPB * H) {
            int ln = t / H, h = t % H;
            int nn = tile * NPB + ln;
            float as = 0.f, ad = 0.f;
#pragma unroll
            for (int c = 0; c < C; c++) {
                float hv = sh[ln][h * C + c];
                as += hv * a_src[h * C + c];
                ad += hv * a_dst[h * C + c];
            }
            g_asrc[nn * H + h] = as;
            g_adst[nn * H + h] = ad;
        }
    }
}

// ---------------------------------------------------------------------------
// Layer-4 transform (64 -> 256): 16 nodes/tile, 4 nodes per thread.
// Output stored head-interleaved: f4[n*128 + pair*4 + head],
// pair = LOCAL channel pair within head ((2q)&31).
// ---------------------------------------------------------------------------
__global__ void k_transform4(const float* __restrict__ W,
                             const float* __restrict__ a_src,
                             const float* __restrict__ a_dst) {
    constexpr int NPB = 16;
    __shared__ __align__(16) float sx[NPB][64];    // 4 KB
    __shared__ __align__(16) float sh[NPB][256];   // 16 KB
    const int t = threadIdx.x;
    const int q = t & 63;
    const int m = t >> 6;
    const int h  = q >> 4;
    const int p0 = (2 * q) & 31;
    __half2* __restrict__ f4 = (__half2*)g_ft4;

    const int ntiles = NNODES / NPB;               // 1250
    for (int tile = blockIdx.x; tile < ntiles; tile += gridDim.x) {
        __syncthreads();
        for (int i = t; i < NPB * 64; i += 256) {
            int nn = tile * NPB + (i >> 6);
            sx[i >> 6][i & 63] = g_featA[nn * 64 + (i & 63)];
        }
        __syncthreads();

        float4 acc0 = make_float4(0.f,0.f,0.f,0.f);
        float4 acc1 = make_float4(0.f,0.f,0.f,0.f);
        float4 acc2 = make_float4(0.f,0.f,0.f,0.f);
        float4 acc3 = make_float4(0.f,0.f,0.f,0.f);
#pragma unroll 4
        for (int k = 0; k < 64; k++) {
            float4 w4 = __ldg((const float4*)&W[k * 256 + 4 * q]);
            float x0 = sx[m * 4 + 0][k];
            float x1 = sx[m * 4 + 1][k];
            float x2 = sx[m * 4 + 2][k];
            float x3 = sx[m * 4 + 3][k];
            acc0.x += x0*w4.x; acc0.y += x0*w4.y; acc0.z += x0*w4.z; acc0.w += x0*w4.w;
            acc1.x += x1*w4.x; acc1.y += x1*w4.y; acc1.z += x1*w4.z; acc1.w += x1*w4.w;
            acc2.x += x2*w4.x; acc2.y += x2*w4.y; acc2.z += x2*w4.z; acc2.w += x2*w4.w;
            acc3.x += x3*w4.x; acc3.y += x3*w4.y; acc3.z += x3*w4.z; acc3.w += x3*w4.w;
        }
        float4 accs[4] = {acc0, acc1, acc2, acc3};
#pragma unroll
        for (int i = 0; i < 4; i++) {
            int nl = m * 4 + i;
            int n  = tile * NPB + nl;
            f4[n * 128 + p0 * 4 + h]       = __floats2half2_rn(accs[i].x, accs[i].y);
            f4[n * 128 + (p0 + 1) * 4 + h] = __floats2half2_rn(accs[i].z, accs[i].w);
            *(float4*)&sh[nl][4 * q] = accs[i];
        }
        __syncthreads();

        if (t < NPB * 4) {                         // 16 nodes x 4 heads
            int nl = t >> 2, hh = t & 3;
            int nn = tile * NPB + nl;
            float as = 0.f, ad = 0.f;
#pragma unroll 8
            for (int c = 0; c < 64; c++) {
                float hv = sh[nl][hh * 64 + c];
                as += hv * a_src[hh * 64 + c];
                ad += hv * a_dst[hh * 64 + c];
            }
            g_asrc[nn * 4 + hh] = as;
            g_adst[nn * 4 + hh] = ad;
        }
    }
}

// ---------------------------------------------------------------------------
// Aggregation, concat layers (H=8,C=8,D=64): FOUR nodes per warp.
// lane = 8*ni + h:  node 4*wid+ni, head h, channels 8h..8h+7 (one 16B gather).
// Exp computed exactly once per (edge, head).
// ---------------------------------------------------------------------------
__global__ void k_agg8(const float* __restrict__ bias) {
    int gw   = (blockIdx.x * blockDim.x + threadIdx.x) >> 5;
    int lane = threadIdx.x & 31;
    const int ni = lane >> 3;
    const int h  = lane & 7;
    const int d  = 4 * gw + ni;
    if (d >= NNODES) return;
    const float adv = g_adst[d * 8 + h];
    const int r0 = g_rowstart[d];
    const int r1 = g_rowstart[d + 1];
    const uint4* __restrict__ ftp = (const uint4*)g_featT;   // row = 8 x 16B

    float den = 0.f;
    float a0 = 0.f, a1 = 0.f, a2 = 0.f, a3 = 0.f;
    float a4 = 0.f, a5 = 0.f, a6 = 0.f, a7 = 0.f;
#pragma unroll 4
    for (int j = r0; j < r1; j++) {
        int s = g_col[j];
        float e = __expf(leaky02(g_asrc[s * 8 + h] + adv));
        den += e;
        uint4 raw = __ldg(&ftp[s * 8 + h]);
        float2 f0 = __half22float2(*(const __half2*)&raw.x);
        float2 f1 = __half22float2(*(const __half2*)&raw.y);
        float2 f2 = __half22float2(*(const __half2*)&raw.z);
        float2 f3 = __half22float2(*(const __half2*)&raw.w);
        a0 += e * f0.x; a1 += e * f0.y;
        a2 += e * f1.x; a3 += e * f1.y;
        a4 += e * f2.x; a5 += e * f2.y;
        a6 += e * f3.x; a7 += e * f3.y;
    }
    float inv = 1.f / den;
    float4 b0 = *(const float4*)&bias[8 * h];
    float4 b1 = *(const float4*)&bias[8 * h + 4];
    float4 o0, o1;
    o0.x = eluf(a0 * inv + b0.x);
    o0.y = eluf(a1 * inv + b0.y);
    o0.z = eluf(a2 * inv + b0.z);
    o0.w = eluf(a3 * inv + b0.w);
    o1.x = eluf(a4 * inv + b1.x);
    o1.y = eluf(a5 * inv + b1.y);
    o1.z = eluf(a6 * inv + b1.z);
    o1.w = eluf(a7 * inv + b1.w);
    *(float4*)&g_featA[d * 64 + 8 * h]     = o0;
    *(float4*)&g_featA[d * 64 + 8 * h + 4] = o1;
}

// ---------------------------------------------------------------------------
// Aggregation, layer 4 (H=4, C=64, mean over heads).  Warp per node.
// Lane owns channel pair (2L,2L+1); ONE 16B gather gives all 4 heads.
// Exp computed once per head (lane&3) and shfl-broadcast within 4-lane group.
// ---------------------------------------------------------------------------
__global__ void k_agg4(const float* __restrict__ bias) {
    int wid  = (blockIdx.x * blockDim.x + threadIdx.x) >> 5;
    int lane = threadIdx.x & 31;
    if (wid >= NNODES) return;
    const int d  = wid;
    const int hm = lane & 3;                       // head this lane computes exp for
    const float adv_m = g_adst[d * 4 + hm];
    const int r0 = g_rowstart[d];
    const int r1 = g_rowstart[d + 1];
    const uint4* __restrict__ ftp = (const uint4*)g_ft4;   // 16B = pair x 4 heads

    float den[4] = {0.f, 0.f, 0.f, 0.f};
    float ax[4]  = {0.f, 0.f, 0.f, 0.f};
    float ay[4]  = {0.f, 0.f, 0.f, 0.f};
#pragma unroll 4
    for (int j = r0; j < r1; j++) {
        int s = g_col[j];
        float em = __expf(leaky02(g_asrc[s * 4 + hm] + adv_m));
        float ev0 = __shfl_sync(0xffffffff, em, 0, 4);
        float ev1 = __shfl_sync(0xffffffff, em, 1, 4);
        float ev2 = __shfl_sync(0xffffffff, em, 2, 4);
        float ev3 = __shfl_sync(0xffffffff, em, 3, 4);
        uint4 raw = __ldg(&ftp[s * 32 + lane]);
        float2 f0 = __half22float2(*(const __half2*)&raw.x);
        float2 f1 = __half22float2(*(const __half2*)&raw.y);
        float2 f2 = __half22float2(*(const __half2*)&raw.z);
        float2 f3 = __half22float2(*(const __half2*)&raw.w);
        den[0] += ev0; ax[0] += ev0 * f0.x; ay[0] += ev0 * f0.y;
        den[1] += ev1; ax[1] += ev1 * f1.x; ay[1] += ev1 * f1.y;
        den[2] += ev2; ax[2] += ev2 * f2.x; ay[2] += ev2 * f2.y;
        den[3] += ev3; ax[3] += ev3 * f3.x; ay[3] += ev3 * f3.y;
    }
    float v1 = 0.f, v2 = 0.f;
#pragma unroll
    for (int hh = 0; hh < 4; hh++) {
        float inv = 1.f / den[hh];
        v1 += ax[hh] * inv;
        v2 += ay[hh] * inv;
    }
    float2 b = *(const float2*)&bias[2 * lane];
    float2 o;
    o.x = eluf(0.25f * v1 + b.x);
    o.y = eluf(0.25f * v2 + b.y);
    *(float2*)&g_featA[d * 64 + 2 * lane] = o;
}

// ---------------------------------------------------------------------------
// Pooling (flag sorted): register run-accumulation, few atomics.
// ---------------------------------------------------------------------------
__global__ void k_pool(const int* __restrict__ fidx, const int* __restrict__ flag, int nf) {
    int c   = threadIdx.x & 63;
    int row = threadIdx.x >> 6;
    int per = (nf + gridDim.x - 1) / gridDim.x;
    int i0  = blockIdx.x * per;
    int i1  = min(i0 + per, nf);
    float acc = 0.f;
    int cur = -1;
    for (int i = i0 + row; i < i1; i += 4) {
        int g = flag[i];
        float v = g_featA[fidx[i] * 64 + c];
        if (g != cur) {
            if (cur >= 0) atomicAdd(&g_fp[cur * 64 + c], acc);
            cur = g; acc = 0.f;
        }
        acc += v;
    }
    if (cur >= 0) atomicAdd(&g_fp[cur * 64 + c], acc);
}

// ---------------------------------------------------------------------------
// Head: z = elu([fp@Wp, h4[dvi]@Wt]); out = z@Wo + bo
// ---------------------------------------------------------------------------
__global__ void k_head(const int* __restrict__ dvi,
                       const float* __restrict__ Wp,
                       const float* __restrict__ Wt,
                       const float* __restrict__ Wo,
                       const float* __restrict__ bo,
                       float* __restrict__ out) {
    __shared__ float sfp[64], stg[64], red[128];
    int g = blockIdx.x, t = threadIdx.x;
    if (t < 64) {
        sfp[t] = g_fp[g * 64 + t];
        stg[t] = g_featA[dvi[g] * 64 + t];
    }
    __syncthreads();
    float acc = 0.f;
    if (t < 64) {
#pragma unroll
        for (int k = 0; k < 64; k++) acc += sfp[k] * Wp[k * 64 + t];
    } else {
        int c = t - 64;
#pragma unroll
        for (int k = 0; k < 64; k++) acc += stg[k] * Wt[k * 64 + c];
    }
    red[t] = eluf(acc) * Wo[t];
    __syncthreads();
    for (int s2 = 64; s2 > 0; s2 >>= 1) {
        if (t < s2) red[t] += red[t + s2];
        __syncthreads();
    }
    if (t == 0) out[g] = red[0] + bo[0];
}

// ---------------------------------------------------------------------------
extern "C" void kernel_launch(void* const* d_in, const int* in_sizes, int n_in,
                              void* d_out, int out_size) {
    const float* x     = (const float*)d_in[0];
    const int*   ei    = (const int*)  d_in[1];
    const int*   fidx  = (const int*)  d_in[2];
    const int*   flag  = (const int*)  d_in[3];
    const int*   dvi   = (const int*)  d_in[4];
    const float* W1    = (const float*)d_in[5];
    const float* as1   = (const float*)d_in[6];
    const float* ad1   = (const float*)d_in[7];
    const float* b1    = (const float*)d_in[8];
    const float* W2    = (const float*)d_in[9];
    const float* as2   = (const float*)d_in[10];
    const float* ad2   = (const float*)d_in[11];
    const float* b2    = (const float*)d_in[12];
    const float* W3    = (const float*)d_in[13];
    const float* as3   = (const float*)d_in[14];
    const float* ad3   = (const float*)d_in[15];
    const float* b3    = (const float*)d_in[16];
    const float* W4    = (const float*)d_in[17];
    const float* as4   = (const float*)d_in[18];
    const float* ad4   = (const float*)d_in[19];
    const float* b4    = (const float*)d_in[20];
    const float* Wp    = (const float*)d_in[21];
    const float* Wt    = (const float*)d_in[22];
    const float* Wo    = (const float*)d_in[23];
    const float* bo    = (const float*)d_in[24];
    float* out = (float*)d_out;

    const int nf  = in_sizes[2];                     // 8000
    const int EB  = (ETOT + 255) / 256;
    const int AB8 = (NNODES / 4 * 32 + 255) / 256;   // 625 (4 nodes/warp)
    const int AB4 = (NNODES * 32 + 255) / 256;       // 2500

    // ---- CSR build ----
    k_count<<<EB, 256>>>(ei);
    k_scan<<<1, SCAN_T>>>();
    k_fill<<<EB, 256>>>(ei);

    // ---- Layer 1: 16 -> 8x8 concat ----
    k_transform64<16, false><<<625, 256>>>(x, W1, as1, ad1);
    k_agg8<<<AB8, 256>>>(b1);
    // ---- Layer 2 ----
    k_transform64<64, true><<<625, 256>>>(nullptr, W2, as2, ad2);
    k_agg8<<<AB8, 256>>>(b2);
    // ---- Layer 3 ----
    k_transform64<64, true><<<625, 256>>>(nullptr, W3, as3, ad3);
    k_agg8<<<AB8, 256>>>(b3);
    // ---- Layer 4: 64 -> 4 heads x 64, mean ----
    k_transform4<<<1250, 256>>>(W4, as4, ad4);
    k_agg4<<<AB4, 256>>>(b4);

    // ---- Pool + head ----
    k_pool<<<32, 256>>>(fidx, flag, nf);
    k_head<<<NG, 128>>>(dvi, Wp, Wt, Wo, bo, out);
}

// round 12
// speedup vs baseline: 1.4439x; 1.0042x over previous
#include <cuda_runtime.h>
#include <cuda_fp16.h>
#include <math.h>

// ---------------------------------------------------------------------------
// GATNet: 4x GATConv + pool + MLP head.  Multi-kernel, CSR-by-dst,
// single-pass softmax, fp16 feature gathers.
// R12: CSR build overlapped with transform1 via stream fork (parallel graph
// branches); transform64 grid doubled (1 tile/block).
// ---------------------------------------------------------------------------

#define NNODES 20000
#define E0     320000
#define ETOT   (E0 + NNODES)
#define NG     8
#define SCAN_T 1024
#define SCAN_CHUNK ((NNODES + SCAN_T - 1) / SCAN_T)

// Scratch (device globals; no allocations allowed)
__device__ __align__(16) float  g_featA[NNODES * 64];   // layer input (post-ELU) fp32
__device__ __align__(16) __half g_featT[NNODES * 64];   // L1-3 transformed feats fp16
__device__ __align__(16) __half g_ft4  [NNODES * 256];  // L4 feats fp16, [pair32][head4] half2
__device__ __align__(16) float  g_asrc [NNODES * 8];
__device__ __align__(16) float  g_adst [NNODES * 8];
__device__ float g_fp[NG * 64];
// CSR by destination. g_cnt zero on entry (static init; re-zeroed in k_fill).
__device__ int g_cnt[NNODES];
__device__ int g_rowstart[NNODES + 1];
__device__ int g_cursor[NNODES];
__device__ int g_col[ETOT];

__device__ __forceinline__ float leaky02(float v) { return fmaxf(v, 0.2f * v); }
__device__ __forceinline__ float eluf(float v)    { return v > 0.f ? v : (__expf(v) - 1.f); }

// ---------------------------------------------------------------------------
// CSR build
// ---------------------------------------------------------------------------
__global__ void k_count(const int* __restrict__ ei) {
    int e = blockIdx.x * blockDim.x + threadIdx.x;
    if (e >= ETOT) return;
    int d = (e < E0) ? ei[E0 + e] : (e - E0);
    atomicAdd(&g_cnt[d], 1);
}
__global__ void k_scan() {
    __shared__ int sp[SCAN_T];
    int t = threadIdx.x;
    if (t < NG * 64) g_fp[t] = 0.f;          // zero pool accumulator
    int b0 = t * SCAN_CHUNK;
    int b1 = min(b0 + SCAN_CHUNK, NNODES);
    int sum = 0;
    for (int i = b0; i < b1; i++) sum += g_cnt[i];
    sp[t] = sum;
    __syncthreads();
    for (int off = 1; off < SCAN_T; off <<= 1) {
        int v = (t >= off) ? sp[t - off] : 0;
        __syncthreads();
        sp[t] += v;
        __syncthreads();
    }
    int base = (t == 0) ? 0 : sp[t - 1];
    for (int i = b0; i < b1; i++) {
        g_rowstart[i] = base;
        g_cursor[i]   = base;
        base += g_cnt[i];
    }
    if (t == SCAN_T - 1) g_rowstart[NNODES] = base;
}
__global__ void k_fill(const int* __restrict__ ei) {
    int e = blockIdx.x * blockDim.x + threadIdx.x;
    if (e < NNODES) g_cnt[e] = 0;            // self-clean for next call
    if (e >= ETOT) return;
    int s, d;
    if (e < E0) { s = ei[e]; d = ei[E0 + e]; }
    else        { s = e - E0; d = e - E0; }
    int pos = atomicAdd(&g_cursor[d], 1);
    g_col[pos] = s;
}

// ---------------------------------------------------------------------------
// Transform for layers 1-3 (D=64).  16 nodes/block-tile, W staged in smem.
// ---------------------------------------------------------------------------
template<int IN, bool USE_G>
__global__ void k_transform64(const float* __restrict__ xin,
                              const float* __restrict__ W,
                              const float* __restrict__ a_src,
                              const float* __restrict__ a_dst) {
    constexpr int D = 64, H = 8, C = 8, NPB = 16;
    __shared__ __align__(16) float sW[IN * D];
    __shared__ __align__(16) float sx[NPB][IN];
    __shared__ __align__(16) float sh[NPB][D];
    const int t  = threadIdx.x;
    const int li = t / 16;
    const int q  = t % 16;
    const float* __restrict__ xp = USE_G ? (const float*)g_featA : xin;

    for (int i = t; i < IN * D / 4; i += 256)
        ((float4*)sW)[i] = ((const float4*)W)[i];

    const int ntiles = NNODES / NPB;           // 1250
    for (int tile = blockIdx.x; tile < ntiles; tile += gridDim.x) {
        __syncthreads();
        for (int i = t; i < NPB * IN; i += 256) {
            int nn = tile * NPB + i / IN;
            sx[i / IN][i % IN] = xp[nn * IN + i % IN];
        }
        __syncthreads();

        const int n = tile * NPB + li;
        float4 acc = make_float4(0.f, 0.f, 0.f, 0.f);
#pragma unroll
        for (int i = 0; i < IN; i++) {
            float xv = sx[li][i];
            float4 w4 = *(const float4*)&sW[i * D + 4 * q];
            acc.x += xv * w4.x; acc.y += xv * w4.y;
            acc.z += xv * w4.z; acc.w += xv * w4.w;
        }
        {
            __half2* dst = (__half2*)&g_featT[n * D + 4 * q];
            dst[0] = __floats2half2_rn(acc.x, acc.y);
            dst[1] = __floats2half2_rn(acc.z, acc.w);
            *(float4*)&sh[li][4 * q] = acc;
        }
        __syncthreads();

        if (t < NPB * H) {
            int ln = t / H, h = t % H;
            int nn = tile * NPB + ln;
            float as = 0.f, ad = 0.f;
#pragma unroll
            for (int c = 0; c < C; c++) {
                float hv = sh[ln][h * C + c];
                as += hv * a_src[h * C + c];
                ad += hv * a_dst[h * C + c];
            }
            g_asrc[nn * H + h] = as;
            g_adst[nn * H + h] = ad;
        }
    }
}

// ---------------------------------------------------------------------------
// Layer-4 transform (64 -> 256): 16 nodes/tile, 4 nodes per thread.
// Output stored head-interleaved: f4[n*128 + pair*4 + head],
// pair = LOCAL channel pair within head ((2q)&31).
// ---------------------------------------------------------------------------
__global__ void k_transform4(const float* __restrict__ W,
                             const float* __restrict__ a_src,
                             const float* __restrict__ a_dst) {
    constexpr int NPB = 16;
    __shared__ __align__(16) float sx[NPB][64];    // 4 KB
    __shared__ __align__(16) float sh[NPB][256];   // 16 KB
    const int t = threadIdx.x;
    const int q = t & 63;
    const int m = t >> 6;
    const int h  = q >> 4;
    const int p0 = (2 * q) & 31;
    __half2* __restrict__ f4 = (__half2*)g_ft4;

    const int ntiles = NNODES / NPB;               // 1250
    for (int tile = blockIdx.x; tile < ntiles; tile += gridDim.x) {
        __syncthreads();
        for (int i = t; i < NPB * 64; i += 256) {
            int nn = tile * NPB + (i >> 6);
            sx[i >> 6][i & 63] = g_featA[nn * 64 + (i & 63)];
        }
        __syncthreads();

        float4 acc0 = make_float4(0.f,0.f,0.f,0.f);
        float4 acc1 = make_float4(0.f,0.f,0.f,0.f);
        float4 acc2 = make_float4(0.f,0.f,0.f,0.f);
        float4 acc3 = make_float4(0.f,0.f,0.f,0.f);
#pragma unroll 4
        for (int k = 0; k < 64; k++) {
            float4 w4 = __ldg((const float4*)&W[k * 256 + 4 * q]);
            float x0 = sx[m * 4 + 0][k];
            float x1 = sx[m * 4 + 1][k];
            float x2 = sx[m * 4 + 2][k];
            float x3 = sx[m * 4 + 3][k];
            acc0.x += x0*w4.x; acc0.y += x0*w4.y; acc0.z += x0*w4.z; acc0.w += x0*w4.w;
            acc1.x += x1*w4.x; acc1.y += x1*w4.y; acc1.z += x1*w4.z; acc1.w += x1*w4.w;
            acc2.x += x2*w4.x; acc2.y += x2*w4.y; acc2.z += x2*w4.z; acc2.w += x2*w4.w;
            acc3.x += x3*w4.x; acc3.y += x3*w4.y; acc3.z += x3*w4.z; acc3.w += x3*w4.w;
        }
        float4 accs[4] = {acc0, acc1, acc2, acc3};
#pragma unroll
        for (int i = 0; i < 4; i++) {
            int nl = m * 4 + i;
            int n  = tile * NPB + nl;
            f4[n * 128 + p0 * 4 + h]       = __floats2half2_rn(accs[i].x, accs[i].y);
            f4[n * 128 + (p0 + 1) * 4 + h] = __floats2half2_rn(accs[i].z, accs[i].w);
            *(float4*)&sh[nl][4 * q] = accs[i];
        }
        __syncthreads();

        if (t < NPB * 4) {                         // 16 nodes x 4 heads
            int nl = t >> 2, hh = t & 3;
            int nn = tile * NPB + nl;
            float as = 0.f, ad = 0.f;
#pragma unroll 8
            for (int c = 0; c < 64; c++) {
                float hv = sh[nl][hh * 64 + c];
                as += hv * a_src[hh * 64 + c];
                ad += hv * a_dst[hh * 64 + c];
            }
            g_asrc[nn * 4 + hh] = as;
            g_adst[nn * 4 + hh] = ad;
        }
    }
}

// ---------------------------------------------------------------------------
// Aggregation, concat layers (H=8,C=8,D=64): FOUR nodes per warp.
// lane = 8*ni + h:  node 4*wid+ni, head h, channels 8h..8h+7 (one 16B gather).
// ---------------------------------------------------------------------------
__global__ void k_agg8(const float* __restrict__ bias) {
    int gw   = (blockIdx.x * blockDim.x + threadIdx.x) >> 5;
    int lane = threadIdx.x & 31;
    const int ni = lane >> 3;
    const int h  = lane & 7;
    const int d  = 4 * gw + ni;
    if (d >= NNODES) return;
    const float adv = g_adst[d * 8 + h];
    const int r0 = g_rowstart[d];
    const int r1 = g_rowstart[d + 1];
    const uint4* __restrict__ ftp = (const uint4*)g_featT;   // row = 8 x 16B

    float den = 0.f;
    float a0 = 0.f, a1 = 0.f, a2 = 0.f, a3 = 0.f;
    float a4 = 0.f, a5 = 0.f, a6 = 0.f, a7 = 0.f;
#pragma unroll 4
    for (int j = r0; j < r1; j++) {
        int s = g_col[j];
        float e = __expf(leaky02(g_asrc[s * 8 + h] + adv));
        den += e;
        uint4 raw = __ldg(&ftp[s * 8 + h]);
        float2 f0 = __half22float2(*(const __half2*)&raw.x);
        float2 f1 = __half22float2(*(const __half2*)&raw.y);
        float2 f2 = __half22float2(*(const __half2*)&raw.z);
        float2 f3 = __half22float2(*(const __half2*)&raw.w);
        a0 += e * f0.x; a1 += e * f0.y;
        a2 += e * f1.x; a3 += e * f1.y;
        a4 += e * f2.x; a5 += e * f2.y;
        a6 += e * f3.x; a7 += e * f3.y;
    }
    float inv = 1.f / den;
    float4 b0 = *(const float4*)&bias[8 * h];
    float4 b1 = *(const float4*)&bias[8 * h + 4];
    float4 o0, o1;
    o0.x = eluf(a0 * inv + b0.x);
    o0.y = eluf(a1 * inv + b0.y);
    o0.z = eluf(a2 * inv + b0.z);
    o0.w = eluf(a3 * inv + b0.w);
    o1.x = eluf(a4 * inv + b1.x);
    o1.y = eluf(a5 * inv + b1.y);
    o1.z = eluf(a6 * inv + b1.z);
    o1.w = eluf(a7 * inv + b1.w);
    *(float4*)&g_featA[d * 64 + 8 * h]     = o0;
    *(float4*)&g_featA[d * 64 + 8 * h + 4] = o1;
}

// ---------------------------------------------------------------------------
// Aggregation, layer 4 (H=4, C=64, mean over heads).  Warp per node.
// Lane owns channel pair (2L,2L+1); ONE 16B gather gives all 4 heads.
// Exp computed once per head (lane&3) and shfl-broadcast within 4-lane group.
// ---------------------------------------------------------------------------
__global__ void k_agg4(const float* __restrict__ bias) {
    int wid  = (blockIdx.x * blockDim.x + threadIdx.x) >> 5;
    int lane = threadIdx.x & 31;
    if (wid >= NNODES) return;
    const int d  = wid;
    const int hm = lane & 3;
    const float adv_m = g_adst[d * 4 + hm];
    const int r0 = g_rowstart[d];
    const int r1 = g_rowstart[d + 1];
    const uint4* __restrict__ ftp = (const uint4*)g_ft4;   // 16B = pair x 4 heads

    float den[4] = {0.f, 0.f, 0.f, 0.f};
    float ax[4]  = {0.f, 0.f, 0.f, 0.f};
    float ay[4]  = {0.f, 0.f, 0.f, 0.f};
#pragma unroll 4
    for (int j = r0; j < r1; j++) {
        int s = g_col[j];
        float em = __expf(leaky02(g_asrc[s * 4 + hm] + adv_m));
        float ev0 = __shfl_sync(0xffffffff, em, 0, 4);
        float ev1 = __shfl_sync(0xffffffff, em, 1, 4);
        float ev2 = __shfl_sync(0xffffffff, em, 2, 4);
        float ev3 = __shfl_sync(0xffffffff, em, 3, 4);
        uint4 raw = __ldg(&ftp[s * 32 + lane]);
        float2 f0 = __half22float2(*(const __half2*)&raw.x);
        float2 f1 = __half22float2(*(const __half2*)&raw.y);
        float2 f2 = __half22float2(*(const __half2*)&raw.z);
        float2 f3 = __half22float2(*(const __half2*)&raw.w);
        den[0] += ev0; ax[0] += ev0 * f0.x; ay[0] += ev0 * f0.y;
        den[1] += ev1; ax[1] += ev1 * f1.x; ay[1] += ev1 * f1.y;
        den[2] += ev2; ax[2] += ev2 * f2.x; ay[2] += ev2 * f2.y;
        den[3] += ev3; ax[3] += ev3 * f3.x; ay[3] += ev3 * f3.y;
    }
    float v1 = 0.f, v2 = 0.f;
#pragma unroll
    for (int hh = 0; hh < 4; hh++) {
        float inv = 1.f / den[hh];
        v1 += ax[hh] * inv;
        v2 += ay[hh] * inv;
    }
    float2 b = *(const float2*)&bias[2 * lane];
    float2 o;
    o.x = eluf(0.25f * v1 + b.x);
    o.y = eluf(0.25f * v2 + b.y);
    *(float2*)&g_featA[d * 64 + 2 * lane] = o;
}

// ---------------------------------------------------------------------------
// Pooling (flag sorted): register run-accumulation, few atomics.
// ---------------------------------------------------------------------------
__global__ void k_pool(const int* __restrict__ fidx, const int* __restrict__ flag, int nf) {
    int c   = threadIdx.x & 63;
    int row = threadIdx.x >> 6;
    int per = (nf + gridDim.x - 1) / gridDim.x;
    int i0  = blockIdx.x * per;
    int i1  = min(i0 + per, nf);
    float acc = 0.f;
    int cur = -1;
    for (int i = i0 + row; i < i1; i += 4) {
        int g = flag[i];
        float v = g_featA[fidx[i] * 64 + c];
        if (g != cur) {
            if (cur >= 0) atomicAdd(&g_fp[cur * 64 + c], acc);
            cur = g; acc = 0.f;
        }
        acc += v;
    }
    if (cur >= 0) atomicAdd(&g_fp[cur * 64 + c], acc);
}

// ---------------------------------------------------------------------------
// Head: z = elu([fp@Wp, h4[dvi]@Wt]); out = z@Wo + bo
// ---------------------------------------------------------------------------
__global__ void k_head(const int* __restrict__ dvi,
                       const float* __restrict__ Wp,
                       const float* __restrict__ Wt,
                       const float* __restrict__ Wo,
                       const float* __restrict__ bo,
                       float* __restrict__ out) {
    __shared__ float sfp[64], stg[64], red[128];
    int g = blockIdx.x, t = threadIdx.x;
    if (t < 64) {
        sfp[t] = g_fp[g * 64 + t];
        stg[t] = g_featA[dvi[g] * 64 + t];
    }
    __syncthreads();
    float acc = 0.f;
    if (t < 64) {
#pragma unroll
        for (int k = 0; k < 64; k++) acc += sfp[k] * Wp[k * 64 + t];
    } else {
        int c = t - 64;
#pragma unroll
        for (int k = 0; k < 64; k++) acc += stg[k] * Wt[k * 64 + c];
    }
    red[t] = eluf(acc) * Wo[t];
    __syncthreads();
    for (int s2 = 64; s2 > 0; s2 >>= 1) {
        if (t < s2) red[t] += red[t + s2];
        __syncthreads();
    }
    if (t == 0) out[g] = red[0] + bo[0];
}

// ---------------------------------------------------------------------------
extern "C" void kernel_launch(void* const* d_in, const int* in_sizes, int n_in,
                              void* d_out, int out_size) {
    const float* x     = (const float*)d_in[0];
    const int*   ei    = (const int*)  d_in[1];
    const int*   fidx  = (const int*)  d_in[2];
    const int*   flag  = (const int*)  d_in[3];
    const int*   dvi   = (const int*)  d_in[4];
    const float* W1    = (const float*)d_in[5];
    const float* as1   = (const float*)d_in[6];
    const float* ad1   = (const float*)d_in[7];
    const float* b1    = (const float*)d_in[8];
    const float* W2    = (const float*)d_in[9];
    const float* as2   = (const float*)d_in[10];
    const float* ad2   = (const float*)d_in[11];
    const float* b2    = (const float*)d_in[12];
    const float* W3    = (const float*)d_in[13];
    const float* as3   = (const float*)d_in[14];
    const float* ad3   = (const float*)d_in[15];
    const float* b3    = (const float*)d_in[16];
    const float* W4    = (const float*)d_in[17];
    const float* as4   = (const float*)d_in[18];
    const float* ad4   = (const float*)d_in[19];
    const float* b4    = (const float*)d_in[20];
    const float* Wp    = (const float*)d_in[21];
    const float* Wt    = (const float*)d_in[22];
    const float* Wo    = (const float*)d_in[23];
    const float* bo    = (const float*)d_in[24];
    float* out = (float*)d_out;

    const int nf  = in_sizes[2];                     // 8000
    const int EB  = (ETOT + 255) / 256;
    const int AB8 = (NNODES / 4 * 32 + 255) / 256;   // 625 (4 nodes/warp)
    const int AB4 = (NNODES * 32 + 255) / 256;       // 2500

    // One-time stream/event setup (resource creation only; work per call is
    // identical -- all kernels are launched every call).
    static cudaStream_t s2 = nullptr;
    static cudaEvent_t evFork = nullptr, evJoin = nullptr;
    if (s2 == nullptr) {
        cudaStreamCreateWithFlags(&s2, cudaStreamNonBlocking);
        cudaEventCreateWithFlags(&evFork, cudaEventDisableTiming);
        cudaEventCreateWithFlags(&evJoin, cudaEventDisableTiming);
    }

    // ---- Fork: CSR build on s2, transform1 on main stream ----
    cudaEventRecord(evFork, 0);
    cudaStreamWaitEvent(s2, evFork, 0);
    k_count<<<EB, 256, 0, s2>>>(ei);
    k_scan<<<1, SCAN_T, 0, s2>>>();
    k_fill<<<EB, 256, 0, s2>>>(ei);
    cudaEventRecord(evJoin, s2);

    k_transform64<16, false><<<1250, 256>>>(x, W1, as1, ad1);

    // ---- Join: agg needs both CSR and transform1 ----
    cudaStreamWaitEvent(0, evJoin, 0);

    // ---- Layer 1 agg ----
    k_agg8<<<AB8, 256>>>(b1);
    // ---- Layer 2 ----
    k_transform64<64, true><<<1250, 256>>>(nullptr, W2, as2, ad2);
    k_agg8<<<AB8, 256>>>(b2);
    // ---- Layer 3 ----
    k_transform64<64, true><<<1250, 256>>>(nullptr, W3, as3, ad3);
    k_agg8<<<AB8, 256>>>(b3);
    // ---- Layer 4: 64 -> 4 heads x 64, mean ----
    k_transform4<<<1250, 256>>>(W4, as4, ad4);
    k_agg4<<<AB4, 256>>>(b4);

    // ---- Pool + head ----
    k_pool<<<32, 256>>>(fidx, flag, nf);
    k_head<<<NG, 128>>>(dvi, Wp, Wt, Wo, bo, out);
}

// round 13
// speedup vs baseline: 1.4609x; 1.0118x over previous
#include <cuda_runtime.h>
#include <cuda_fp16.h>
#include <math.h>

// ---------------------------------------------------------------------------
// GATNet: 4x GATConv + pool + MLP head.  Multi-kernel, CSR-by-dst,
// single-pass softmax, fp16 feature gathers.
// R13: ILP-4 CSR build (count/fill 4 edges/thread); pool+head fused into one
// 8-block kernel (binary search over sorted flag, no atomics).
// ---------------------------------------------------------------------------

#define NNODES 20000
#define E0     320000
#define ETOT   (E0 + NNODES)
#define NG     8
#define SCAN_T 1024
#define SCAN_CHUNK ((NNODES + SCAN_T - 1) / SCAN_T)

// Scratch (device globals; no allocations allowed)
__device__ __align__(16) float  g_featA[NNODES * 64];   // layer input (post-ELU) fp32
__device__ __align__(16) __half g_featT[NNODES * 64];   // L1-3 transformed feats fp16
__device__ __align__(16) __half g_ft4  [NNODES * 256];  // L4 feats fp16, [pair32][head4] half2
__device__ __align__(16) float  g_asrc [NNODES * 8];
__device__ __align__(16) float  g_adst [NNODES * 8];
// CSR by destination. g_cnt zero on entry (static init; re-zeroed in k_fill).
__device__ int g_cnt[NNODES];
__device__ int g_rowstart[NNODES + 1];
__device__ int g_cursor[NNODES];
__device__ int g_col[ETOT];

__device__ __forceinline__ float leaky02(float v) { return fmaxf(v, 0.2f * v); }
__device__ __forceinline__ float eluf(float v)    { return v > 0.f ? v : (__expf(v) - 1.f); }

// ---------------------------------------------------------------------------
// CSR build: 4 edges per thread for MLP (count/fill are latency-bound).
// ---------------------------------------------------------------------------
#define CSR_BLKS 334
#define CSR_STRIDE (CSR_BLKS * 256)

__global__ void k_count(const int* __restrict__ ei) {
    int gtid = blockIdx.x * blockDim.x + threadIdx.x;
    int dd[4]; bool ok[4];
#pragma unroll
    for (int k = 0; k < 4; k++) {
        int e = gtid + k * CSR_STRIDE;
        ok[k] = (e < ETOT);
        dd[k] = ok[k] ? ((e < E0) ? ei[E0 + e] : (e - E0)) : 0;
    }
#pragma unroll
    for (int k = 0; k < 4; k++)
        if (ok[k]) atomicAdd(&g_cnt[dd[k]], 1);
}
__global__ void k_scan() {
    __shared__ int sp[SCAN_T];
    int t = threadIdx.x;
    int b0 = t * SCAN_CHUNK;
    int b1 = min(b0 + SCAN_CHUNK, NNODES);
    int sum = 0;
    for (int i = b0; i < b1; i++) sum += g_cnt[i];
    sp[t] = sum;
    __syncthreads();
    for (int off = 1; off < SCAN_T; off <<= 1) {
        int v = (t >= off) ? sp[t - off] : 0;
        __syncthreads();
        sp[t] += v;
        __syncthreads();
    }
    int base = (t == 0) ? 0 : sp[t - 1];
    for (int i = b0; i < b1; i++) {
        g_rowstart[i] = base;
        g_cursor[i]   = base;
        base += g_cnt[i];
    }
    if (t == SCAN_T - 1) g_rowstart[NNODES] = base;
}
__global__ void k_fill(const int* __restrict__ ei) {
    int gtid = blockIdx.x * blockDim.x + threadIdx.x;
    if (gtid < NNODES) g_cnt[gtid] = 0;                 // self-clean (NNODES < CSR_STRIDE)
    int ss[4], dd[4]; bool ok[4];
#pragma unroll
    for (int k = 0; k < 4; k++) {
        int e = gtid + k * CSR_STRIDE;
        ok[k] = (e < ETOT);
        if (ok[k]) {
            if (e < E0) { ss[k] = ei[e]; dd[k] = ei[E0 + e]; }
            else        { ss[k] = e - E0; dd[k] = e - E0; }
        }
    }
#pragma unroll
    for (int k = 0; k < 4; k++) {
        if (ok[k]) {
            int pos = atomicAdd(&g_cursor[dd[k]], 1);
            g_col[pos] = ss[k];
        }
    }
}

// ---------------------------------------------------------------------------
// Transform for layers 1-3 (D=64).  16 nodes/block-tile, W staged in smem.
// ---------------------------------------------------------------------------
template<int IN, bool USE_G>
__global__ void k_transform64(const float* __restrict__ xin,
                              const float* __restrict__ W,
                              const float* __restrict__ a_src,
                              const float* __restrict__ a_dst) {
    constexpr int D = 64, H = 8, C = 8, NPB = 16;
    __shared__ __align__(16) float sW[IN * D];
    __shared__ __align__(16) float sx[NPB][IN];
    __shared__ __align__(16) float sh[NPB][D];
    const int t  = threadIdx.x;
    const int li = t / 16;
    const int q  = t % 16;
    const float* __restrict__ xp = USE_G ? (const float*)g_featA : xin;

    for (int i = t; i < IN * D / 4; i += 256)
        ((float4*)sW)[i] = ((const float4*)W)[i];

    const int tile = blockIdx.x;               // grid = 1250 = NNODES/16
    {
        for (int i = t; i < NPB * IN; i += 256) {
            int nn = tile * NPB + i / IN;
            sx[i / IN][i % IN] = xp[nn * IN + i % IN];
        }
        __syncthreads();

        const int n = tile * NPB + li;
        float4 acc = make_float4(0.f, 0.f, 0.f, 0.f);
#pragma unroll
        for (int i = 0; i < IN; i++) {
            float xv = sx[li][i];
            float4 w4 = *(const float4*)&sW[i * D + 4 * q];
            acc.x += xv * w4.x; acc.y += xv * w4.y;
            acc.z += xv * w4.z; acc.w += xv * w4.w;
        }
        {
            __half2* dst = (__half2*)&g_featT[n * D + 4 * q];
            dst[0] = __floats2half2_rn(acc.x, acc.y);
            dst[1] = __floats2half2_rn(acc.z, acc.w);
            *(float4*)&sh[li][4 * q] = acc;
        }
        __syncthreads();

        if (t < NPB * H) {
            int ln = t / H, h = t % H;
            int nn = tile * NPB + ln;
            float as = 0.f, ad = 0.f;
#pragma unroll
            for (int c = 0; c < C; c++) {
                float hv = sh[ln][h * C + c];
                as += hv * a_src[h * C + c];
                ad += hv * a_dst[h * C + c];
            }
            g_asrc[nn * H + h] = as;
            g_adst[nn * H + h] = ad;
        }
    }
}

// ---------------------------------------------------------------------------
// Layer-4 transform (64 -> 256): 16 nodes/tile, 4 nodes per thread.
// Output head-interleaved: f4[n*128 + pair*4 + head], pair local ((2q)&31).
// ---------------------------------------------------------------------------
__global__ void k_transform4(const float* __restrict__ W,
                             const float* __restrict__ a_src,
                             const float* __restrict__ a_dst) {
    constexpr int NPB = 16;
    __shared__ __align__(16) float sx[NPB][64];    // 4 KB
    __shared__ __align__(16) float sh[NPB][256];   // 16 KB
    const int t = threadIdx.x;
    const int q = t & 63;
    const int m = t >> 6;
    const int h  = q >> 4;
    const int p0 = (2 * q) & 31;
    __half2* __restrict__ f4 = (__half2*)g_ft4;

    const int tile = blockIdx.x;                   // grid = 1250
    {
        for (int i = t; i < NPB * 64; i += 256) {
            int nn = tile * NPB + (i >> 6);
            sx[i >> 6][i & 63] = g_featA[nn * 64 + (i & 63)];
        }
        __syncthreads();

        float4 acc0 = make_float4(0.f,0.f,0.f,0.f);
        float4 acc1 = make_float4(0.f,0.f,0.f,0.f);
        float4 acc2 = make_float4(0.f,0.f,0.f,0.f);
        float4 acc3 = make_float4(0.f,0.f,0.f,0.f);
#pragma unroll 4
        for (int k = 0; k < 64; k++) {
            float4 w4 = __ldg((const float4*)&W[k * 256 + 4 * q]);
            float x0 = sx[m * 4 + 0][k];
            float x1 = sx[m * 4 + 1][k];
            float x2 = sx[m * 4 + 2][k];
            float x3 = sx[m * 4 + 3][k];
            acc0.x += x0*w4.x; acc0.y += x0*w4.y; acc0.z += x0*w4.z; acc0.w += x0*w4.w;
            acc1.x += x1*w4.x; acc1.y += x1*w4.y; acc1.z += x1*w4.z; acc1.w += x1*w4.w;
            acc2.x += x2*w4.x; acc2.y += x2*w4.y; acc2.z += x2*w4.z; acc2.w += x2*w4.w;
            acc3.x += x3*w4.x; acc3.y += x3*w4.y; acc3.z += x3*w4.z; acc3.w += x3*w4.w;
        }
        float4 accs[4] = {acc0, acc1, acc2, acc3};
#pragma unroll
        for (int i = 0; i < 4; i++) {
            int nl = m * 4 + i;
            int n  = tile * NPB + nl;
            f4[n * 128 + p0 * 4 + h]       = __floats2half2_rn(accs[i].x, accs[i].y);
            f4[n * 128 + (p0 + 1) * 4 + h] = __floats2half2_rn(accs[i].z, accs[i].w);
            *(float4*)&sh[nl][4 * q] = accs[i];
        }
        __syncthreads();

        if (t < NPB * 4) {                         // 16 nodes x 4 heads
            int nl = t >> 2, hh = t & 3;
            int nn = tile * NPB + nl;
            float as = 0.f, ad = 0.f;
#pragma unroll 8
            for (int c = 0; c < 64; c++) {
                float hv = sh[nl][hh * 64 + c];
                as += hv * a_src[hh * 64 + c];
                ad += hv * a_dst[hh * 64 + c];
            }
            g_asrc[nn * 4 + hh] = as;
            g_adst[nn * 4 + hh] = ad;
        }
    }
}

// ---------------------------------------------------------------------------
// Aggregation, concat layers (H=8,C=8,D=64): FOUR nodes per warp.
// lane = 8*ni + h:  node 4*wid+ni, head h, channels 8h..8h+7 (one 16B gather).
// ---------------------------------------------------------------------------
__global__ void k_agg8(const float* __restrict__ bias) {
    int gw   = (blockIdx.x * blockDim.x + threadIdx.x) >> 5;
    int lane = threadIdx.x & 31;
    const int ni = lane >> 3;
    const int h  = lane & 7;
    const int d  = 4 * gw + ni;
    if (d >= NNODES) return;
    const float adv = g_adst[d * 8 + h];
    const int r0 = g_rowstart[d];
    const int r1 = g_rowstart[d + 1];
    const uint4* __restrict__ ftp = (const uint4*)g_featT;   // row = 8 x 16B

    float den = 0.f;
    float a0 = 0.f, a1 = 0.f, a2 = 0.f, a3 = 0.f;
    float a4 = 0.f, a5 = 0.f, a6 = 0.f, a7 = 0.f;
#pragma unroll 4
    for (int j = r0; j < r1; j++) {
        int s = g_col[j];
        float e = __expf(leaky02(g_asrc[s * 8 + h] + adv));
        den += e;
        uint4 raw = __ldg(&ftp[s * 8 + h]);
        float2 f0 = __half22float2(*(const __half2*)&raw.x);
        float2 f1 = __half22float2(*(const __half2*)&raw.y);
        float2 f2 = __half22float2(*(const __half2*)&raw.z);
        float2 f3 = __half22float2(*(const __half2*)&raw.w);
        a0 += e * f0.x; a1 += e * f0.y;
        a2 += e * f1.x; a3 += e * f1.y;
        a4 += e * f2.x; a5 += e * f2.y;
        a6 += e * f3.x; a7 += e * f3.y;
    }
    float inv = 1.f / den;
    float4 b0 = *(const float4*)&bias[8 * h];
    float4 b1 = *(const float4*)&bias[8 * h + 4];
    float4 o0, o1;
    o0.x = eluf(a0 * inv + b0.x);
    o0.y = eluf(a1 * inv + b0.y);
    o0.z = eluf(a2 * inv + b0.z);
    o0.w = eluf(a3 * inv + b0.w);
    o1.x = eluf(a4 * inv + b1.x);
    o1.y = eluf(a5 * inv + b1.y);
    o1.z = eluf(a6 * inv + b1.z);
    o1.w = eluf(a7 * inv + b1.w);
    *(float4*)&g_featA[d * 64 + 8 * h]     = o0;
    *(float4*)&g_featA[d * 64 + 8 * h + 4] = o1;
}

// ---------------------------------------------------------------------------
// Aggregation, layer 4 (H=4, C=64, mean over heads).  Warp per node.
// Lane owns channel pair (2L,2L+1); ONE 16B gather gives all 4 heads.
// Exp computed once per head (lane&3) and shfl-broadcast within 4-lane group.
// ---------------------------------------------------------------------------
__global__ void k_agg4(const float* __restrict__ bias) {
    int wid  = (blockIdx.x * blockDim.x + threadIdx.x) >> 5;
    int lane = threadIdx.x & 31;
    if (wid >= NNODES) return;
    const int d  = wid;
    const int hm = lane & 3;
    const float adv_m = g_adst[d * 4 + hm];
    const int r0 = g_rowstart[d];
    const int r1 = g_rowstart[d + 1];
    const uint4* __restrict__ ftp = (const uint4*)g_ft4;   // 16B = pair x 4 heads

    float den[4] = {0.f, 0.f, 0.f, 0.f};
    float ax[4]  = {0.f, 0.f, 0.f, 0.f};
    float ay[4]  = {0.f, 0.f, 0.f, 0.f};
#pragma unroll 4
    for (int j = r0; j < r1; j++) {
        int s = g_col[j];
        float em = __expf(leaky02(g_asrc[s * 4 + hm] + adv_m));
        float ev0 = __shfl_sync(0xffffffff, em, 0, 4);
        float ev1 = __shfl_sync(0xffffffff, em, 1, 4);
        float ev2 = __shfl_sync(0xffffffff, em, 2, 4);
        float ev3 = __shfl_sync(0xffffffff, em, 3, 4);
        uint4 raw = __ldg(&ftp[s * 32 + lane]);
        float2 f0 = __half22float2(*(const __half2*)&raw.x);
        float2 f1 = __half22float2(*(const __half2*)&raw.y);
        float2 f2 = __half22float2(*(const __half2*)&raw.z);
        float2 f3 = __half22float2(*(const __half2*)&raw.w);
        den[0] += ev0; ax[0] += ev0 * f0.x; ay[0] += ev0 * f0.y;
        den[1] += ev1; ax[1] += ev1 * f1.x; ay[1] += ev1 * f1.y;
        den[2] += ev2; ax[2] += ev2 * f2.x; ay[2] += ev2 * f2.y;
        den[3] += ev3; ax[3] += ev3 * f3.x; ay[3] += ev3 * f3.y;
    }
    float v1 = 0.f, v2 = 0.f;
#pragma unroll
    for (int hh = 0; hh < 4; hh++) {
        float inv = 1.f / den[hh];
        v1 += ax[hh] * inv;
        v2 += ay[hh] * inv;
    }
    float2 b = *(const float2*)&bias[2 * lane];
    float2 o;
    o.x = eluf(0.25f * v1 + b.x);
    o.y = eluf(0.25f * v2 + b.y);
    *(float2*)&g_featA[d * 64 + 2 * lane] = o;
}

// ---------------------------------------------------------------------------
// Fused pool+head: 8 blocks (one per graph).  flag is sorted, so block g
// binary-searches its [lo,hi) range, sums features (no atomics), then
// computes its output scalar.
// ---------------------------------------------------------------------------
__global__ void k_poolhead(const int* __restrict__ fidx, const int* __restrict__ flag,
                           int nf,
                           const int* __restrict__ dvi,
                           const float* __restrict__ Wp,
                           const float* __restrict__ Wt,
                           const float* __restrict__ Wo,
                           const float* __restrict__ bo,
                           float* __restrict__ out) {
    __shared__ float sred[4][64];
    __shared__ float sfp[64], stg[64], red[128];
    const int g = blockIdx.x;
    const int t = threadIdx.x;
    const int c   = t & 63;
    const int row = t >> 6;

    // binary search for range [lo, hi) with flag == g
    int lo = 0, hi = nf;
    {
        int a = 0, b = nf;
        while (a < b) { int m = (a + b) >> 1; if (flag[m] < g) a = m + 1; else b = m; }
        lo = a;
        a = lo; b = nf;
        while (a < b) { int m = (a + b) >> 1; if (flag[m] < g + 1) a = m + 1; else b = m; }
        hi = a;
    }

    float acc = 0.f;
    for (int i = lo + row; i < hi; i += 4)
        acc += g_featA[fidx[i] * 64 + c];
    sred[row][c] = acc;
    __syncthreads();
    if (t < 64) {
        sfp[t] = sred[0][t] + sred[1][t] + sred[2][t] + sred[3][t];
        stg[t] = g_featA[dvi[g] * 64 + t];
    }
    __syncthreads();
    if (t < 128) {
        float a2 = 0.f;
        if (t < 64) {
#pragma unroll
            for (int k = 0; k < 64; k++) a2 += sfp[k] * Wp[k * 64 + t];
        } else {
            int cc = t - 64;
#pragma unroll
            for (int k = 0; k < 64; k++) a2 += stg[k] * Wt[k * 64 + cc];
        }
        red[t] = eluf(a2) * Wo[t];
    }
    __syncthreads();
    for (int s2 = 64; s2 > 0; s2 >>= 1) {
        if (t < s2) red[t] += red[t + s2];
        __syncthreads();
    }
    if (t == 0) out[g] = red[0] + bo[0];
}

// ---------------------------------------------------------------------------
extern "C" void kernel_launch(void* const* d_in, const int* in_sizes, int n_in,
                              void* d_out, int out_size) {
    const float* x     = (const float*)d_in[0];
    const int*   ei    = (const int*)  d_in[1];
    const int*   fidx  = (const int*)  d_in[2];
    const int*   flag  = (const int*)  d_in[3];
    const int*   dvi   = (const int*)  d_in[4];
    const float* W1    = (const float*)d_in[5];
    const float* as1   = (const float*)d_in[6];
    const float* ad1   = (const float*)d_in[7];
    const float* b1    = (const float*)d_in[8];
    const float* W2    = (const float*)d_in[9];
    const float* as2   = (const float*)d_in[10];
    const float* ad2   = (const float*)d_in[11];
    const float* b2    = (const float*)d_in[12];
    const float* W3    = (const float*)d_in[13];
    const float* as3   = (const float*)d_in[14];
    const float* ad3   = (const float*)d_in[15];
    const float* b3    = (const float*)d_in[16];
    const float* W4    = (const float*)d_in[17];
    const float* as4   = (const float*)d_in[18];
    const float* ad4   = (const float*)d_in[19];
    const float* b4    = (const float*)d_in[20];
    const float* Wp    = (const float*)d_in[21];
    const float* Wt    = (const float*)d_in[22];
    const float* Wo    = (const float*)d_in[23];
    const float* bo    = (const float*)d_in[24];
    float* out = (float*)d_out;

    const int nf  = in_sizes[2];                     // 8000
    const int AB8 = (NNODES / 4 * 32 + 255) / 256;   // 625 (4 nodes/warp)
    const int AB4 = (NNODES * 32 + 255) / 256;       // 2500

    // One-time stream/event setup (resource creation only; identical work
    // launched every call).
    static cudaStream_t s2 = nullptr;
    static cudaEvent_t evFork = nullptr, evJoin = nullptr;
    if (s2 == nullptr) {
        cudaStreamCreateWithFlags(&s2, cudaStreamNonBlocking);
        cudaEventCreateWithFlags(&evFork, cudaEventDisableTiming);
        cudaEventCreateWithFlags(&evJoin, cudaEventDisableTiming);
    }

    // ---- Fork: CSR build on s2, transform1 on main stream ----
    cudaEventRecord(evFork, 0);
    cudaStreamWaitEvent(s2, evFork, 0);
    k_count<<<CSR_BLKS, 256, 0, s2>>>(ei);
    k_scan<<<1, SCAN_T, 0, s2>>>();
    k_fill<<<CSR_BLKS, 256, 0, s2>>>(ei);
    cudaEventRecord(evJoin, s2);

    k_transform64<16, false><<<1250, 256>>>(x, W1, as1, ad1);

    // ---- Join ----
    cudaStreamWaitEvent(0, evJoin, 0);

    // ---- Layer 1 agg ----
    k_agg8<<<AB8, 256>>>(b1);
    // ---- Layer 2 ----
    k_transform64<64, true><<<1250, 256>>>(nullptr, W2, as2, ad2);
    k_agg8<<<AB8, 256>>>(b2);
    // ---- Layer 3 ----
    k_transform64<64, true><<<1250, 256>>>(nullptr, W3, as3, ad3);
    k_agg8<<<AB8, 256>>>(b3);
    // ---- Layer 4 ----
    k_transform4<<<1250, 256>>>(W4, as4, ad4);
    k_agg4<<<AB4, 256>>>(b4);

    // ---- Fused pool + head ----
    k_poolhead<<<NG, 256>>>(fidx, flag, nf, dvi, Wp, Wt, Wo, bo, out);
}

// round 14
// speedup vs baseline: 1.4761x; 1.0104x over previous
#include <cuda_runtime.h>
#include <cuda_fp16.h>
#include <math.h>

// ---------------------------------------------------------------------------
// GATNet: 4x GATConv + pool + MLP head.  Multi-kernel, CSR-by-dst,
// single-pass softmax, fp16 feature gathers.
// R14 = R13 + PDL (programmatic stream serialization) on the layer chain:
// each kernel runs its independent prologue concurrent with the
// predecessor's drain, then cudaGridDependencySynchronize().
// ---------------------------------------------------------------------------

#define NNODES 20000
#define E0     320000
#define ETOT   (E0 + NNODES)
#define NG     8
#define SCAN_T 1024
#define SCAN_CHUNK ((NNODES + SCAN_T - 1) / SCAN_T)

__device__ __align__(16) float  g_featA[NNODES * 64];
__device__ __align__(16) __half g_featT[NNODES * 64];
__device__ __align__(16) __half g_ft4  [NNODES * 256];
__device__ __align__(16) float  g_asrc [NNODES * 8];
__device__ __align__(16) float  g_adst [NNODES * 8];
__device__ int g_cnt[NNODES];
__device__ int g_rowstart[NNODES + 1];
__device__ int g_cursor[NNODES];
__device__ int g_col[ETOT];

__device__ __forceinline__ float leaky02(float v) { return fmaxf(v, 0.2f * v); }
__device__ __forceinline__ float eluf(float v)    { return v > 0.f ? v : (__expf(v) - 1.f); }

__device__ __forceinline__ void gdep_sync() {
#if __CUDA_ARCH__ >= 900
    cudaGridDependencySynchronize();
#endif
}

// ---------------------------------------------------------------------------
// CSR build: 4 edges per thread.
// ---------------------------------------------------------------------------
#define CSR_BLKS 334
#define CSR_STRIDE (CSR_BLKS * 256)

__global__ void k_count(const int* __restrict__ ei) {
    int gtid = blockIdx.x * blockDim.x + threadIdx.x;
    int dd[4]; bool ok[4];
#pragma unroll
    for (int k = 0; k < 4; k++) {
        int e = gtid + k * CSR_STRIDE;
        ok[k] = (e < ETOT);
        dd[k] = ok[k] ? ((e < E0) ? ei[E0 + e] : (e - E0)) : 0;
    }
#pragma unroll
    for (int k = 0; k < 4; k++)
        if (ok[k]) atomicAdd(&g_cnt[dd[k]], 1);
}
__global__ void k_scan() {
    __shared__ int sp[SCAN_T];
    int t = threadIdx.x;
    int b0 = t * SCAN_CHUNK;
    int b1 = min(b0 + SCAN_CHUNK, NNODES);
    int sum = 0;
    for (int i = b0; i < b1; i++) sum += g_cnt[i];
    sp[t] = sum;
    __syncthreads();
    for (int off = 1; off < SCAN_T; off <<= 1) {
        int v = (t >= off) ? sp[t - off] : 0;
        __syncthreads();
        sp[t] += v;
        __syncthreads();
    }
    int base = (t == 0) ? 0 : sp[t - 1];
    for (int i = b0; i < b1; i++) {
        g_rowstart[i] = base;
        g_cursor[i]   = base;
        base += g_cnt[i];
    }
    if (t == SCAN_T - 1) g_rowstart[NNODES] = base;
}
__global__ void k_fill(const int* __restrict__ ei) {
    int gtid = blockIdx.x * blockDim.x + threadIdx.x;
    if (gtid < NNODES) g_cnt[gtid] = 0;
    int ss[4], dd[4]; bool ok[4];
#pragma unroll
    for (int k = 0; k < 4; k++) {
        int e = gtid + k * CSR_STRIDE;
        ok[k] = (e < ETOT);
        if (ok[k]) {
            if (e < E0) { ss[k] = ei[e]; dd[k] = ei[E0 + e]; }
            else        { ss[k] = e - E0; dd[k] = e - E0; }
        }
    }
#pragma unroll
    for (int k = 0; k < 4; k++) {
        if (ok[k]) {
            int pos = atomicAdd(&g_cursor[dd[k]], 1);
            g_col[pos] = ss[k];
        }
    }
}

// ---------------------------------------------------------------------------
// Transform layers 1-3 (D=64).  16 nodes/block, W staged in smem.
// PDL: stage W (input) first, then gdep_sync, then read featA.
// ---------------------------------------------------------------------------
template<int IN, bool USE_G, bool PDL>
__global__ void k_transform64(const float* __restrict__ xin,
                              const float* __restrict__ W,
                              const float* __restrict__ a_src,
                              const float* __restrict__ a_dst) {
    constexpr int D = 64, H = 8, C = 8, NPB = 16;
    __shared__ __align__(16) float sW[IN * D];
    __shared__ __align__(16) float sx[NPB][IN];
    __shared__ __align__(16) float sh[NPB][D];
    const int t  = threadIdx.x;
    const int li = t / 16;
    const int q  = t % 16;
    const float* __restrict__ xp = USE_G ? (const float*)g_featA : xin;

    for (int i = t; i < IN * D / 4; i += 256)
        ((float4*)sW)[i] = ((const float4*)W)[i];

    if (PDL) gdep_sync();

    const int tile = blockIdx.x;               // grid = 1250
    for (int i = t; i < NPB * IN; i += 256) {
        int nn = tile * NPB + i / IN;
        sx[i / IN][i % IN] = xp[nn * IN + i % IN];
    }
    __syncthreads();

    const int n = tile * NPB + li;
    float4 acc = make_float4(0.f, 0.f, 0.f, 0.f);
#pragma unroll
    for (int i = 0; i < IN; i++) {
        float xv = sx[li][i];
        float4 w4 = *(const float4*)&sW[i * D + 4 * q];
        acc.x += xv * w4.x; acc.y += xv * w4.y;
        acc.z += xv * w4.z; acc.w += xv * w4.w;
    }
    {
        __half2* dst = (__half2*)&g_featT[n * D + 4 * q];
        dst[0] = __floats2half2_rn(acc.x, acc.y);
        dst[1] = __floats2half2_rn(acc.z, acc.w);
        *(float4*)&sh[li][4 * q] = acc;
    }
    __syncthreads();

    if (t < NPB * H) {
        int ln = t / H, h = t % H;
        int nn = tile * NPB + ln;
        float as = 0.f, ad = 0.f;
#pragma unroll
        for (int c = 0; c < C; c++) {
            float hv = sh[ln][h * C + c];
            as += hv * a_src[h * C + c];
            ad += hv * a_dst[h * C + c];
        }
        g_asrc[nn * H + h] = as;
        g_adst[nn * H + h] = ad;
    }
}

// ---------------------------------------------------------------------------
// Layer-4 transform (64 -> 256): 16 nodes/tile, 4 nodes per thread.
// Head-interleaved output: f4[n*128 + pair*4 + head], pair=(2q)&31.
// ---------------------------------------------------------------------------
__global__ void k_transform4(const float* __restrict__ W,
                             const float* __restrict__ a_src,
                             const float* __restrict__ a_dst) {
    constexpr int NPB = 16;
    __shared__ __align__(16) float sx[NPB][64];
    __shared__ __align__(16) float sh[NPB][256];
    const int t = threadIdx.x;
    const int q = t & 63;
    const int m = t >> 6;
    const int h  = q >> 4;
    const int p0 = (2 * q) & 31;
    __half2* __restrict__ f4 = (__half2*)g_ft4;

    gdep_sync();

    const int tile = blockIdx.x;                   // grid = 1250
    for (int i = t; i < NPB * 64; i += 256) {
        int nn = tile * NPB + (i >> 6);
        sx[i >> 6][i & 63] = g_featA[nn * 64 + (i & 63)];
    }
    __syncthreads();

    float4 acc0 = make_float4(0.f,0.f,0.f,0.f);
    float4 acc1 = make_float4(0.f,0.f,0.f,0.f);
    float4 acc2 = make_float4(0.f,0.f,0.f,0.f);
    float4 acc3 = make_float4(0.f,0.f,0.f,0.f);
#pragma unroll 4
    for (int k = 0; k < 64; k++) {
        float4 w4 = __ldg((const float4*)&W[k * 256 + 4 * q]);
        float x0 = sx[m * 4 + 0][k];
        float x1 = sx[m * 4 + 1][k];
        float x2 = sx[m * 4 + 2][k];
        float x3 = sx[m * 4 + 3][k];
        acc0.x += x0*w4.x; acc0.y += x0*w4.y; acc0.z += x0*w4.z; acc0.w += x0*w4.w;
        acc1.x += x1*w4.x; acc1.y += x1*w4.y; acc1.z += x1*w4.z; acc1.w += x1*w4.w;
        acc2.x += x2*w4.x; acc2.y += x2*w4.y; acc2.z += x2*w4.z; acc2.w += x2*w4.w;
        acc3.x += x3*w4.x; acc3.y += x3*w4.y; acc3.z += x3*w4.z; acc3.w += x3*w4.w;
    }
    float4 accs[4] = {acc0, acc1, acc2, acc3};
#pragma unroll
    for (int i = 0; i < 4; i++) {
        int nl = m * 4 + i;
        int n  = tile * NPB + nl;
        f4[n * 128 + p0 * 4 + h]       = __floats2half2_rn(accs[i].x, accs[i].y);
        f4[n * 128 + (p0 + 1) * 4 + h] = __floats2half2_rn(accs[i].z, accs[i].w);
        *(float4*)&sh[nl][4 * q] = accs[i];
    }
    __syncthreads();

    if (t < NPB * 4) {                         // 16 nodes x 4 heads
        int nl = t >> 2, hh = t & 3;
        int nn = tile * NPB + nl;
        float as = 0.f, ad = 0.f;
#pragma unroll 8
        for (int c = 0; c < 64; c++) {
            float hv = sh[nl][hh * 64 + c];
            as += hv * a_src[hh * 64 + c];
            ad += hv * a_dst[hh * 64 + c];
        }
        g_asrc[nn * 4 + hh] = as;
        g_adst[nn * 4 + hh] = ad;
    }
}

// ---------------------------------------------------------------------------
// Aggregation, concat layers: FOUR nodes per warp, lane = 8*ni + h.
// ---------------------------------------------------------------------------
template<bool PDL>
__global__ void k_agg8(const float* __restrict__ bias) {
    int gw   = (blockIdx.x * blockDim.x + threadIdx.x) >> 5;
    int lane = threadIdx.x & 31;
    const int ni = lane >> 3;
    const int h  = lane & 7;
    const int d  = 4 * gw + ni;
    float4 b0 = *(const float4*)&bias[8 * h];
    float4 b1 = *(const float4*)&bias[8 * h + 4];

    if (PDL) gdep_sync();
    if (d >= NNODES) return;

    const float adv = g_adst[d * 8 + h];
    const int r0 = g_rowstart[d];
    const int r1 = g_rowstart[d + 1];
    const uint4* __restrict__ ftp = (const uint4*)g_featT;

    float den = 0.f;
    float a0 = 0.f, a1 = 0.f, a2 = 0.f, a3 = 0.f;
    float a4 = 0.f, a5 = 0.f, a6 = 0.f, a7 = 0.f;
#pragma unroll 4
    for (int j = r0; j < r1; j++) {
        int s = g_col[j];
        float e = __expf(leaky02(g_asrc[s * 8 + h] + adv));
        den += e;
        uint4 raw = __ldg(&ftp[s * 8 + h]);
        float2 f0 = __half22float2(*(const __half2*)&raw.x);
        float2 f1 = __half22float2(*(const __half2*)&raw.y);
        float2 f2 = __half22float2(*(const __half2*)&raw.z);
        float2 f3 = __half22float2(*(const __half2*)&raw.w);
        a0 += e * f0.x; a1 += e * f0.y;
        a2 += e * f1.x; a3 += e * f1.y;
        a4 += e * f2.x; a5 += e * f2.y;
        a6 += e * f3.x; a7 += e * f3.y;
    }
    float inv = 1.f / den;
    float4 o0, o1;
    o0.x = eluf(a0 * inv + b0.x);
    o0.y = eluf(a1 * inv + b0.y);
    o0.z = eluf(a2 * inv + b0.z);
    o0.w = eluf(a3 * inv + b0.w);
    o1.x = eluf(a4 * inv + b1.x);
    o1.y = eluf(a5 * inv + b1.y);
    o1.z = eluf(a6 * inv + b1.z);
    o1.w = eluf(a7 * inv + b1.w);
    *(float4*)&g_featA[d * 64 + 8 * h]     = o0;
    *(float4*)&g_featA[d * 64 + 8 * h + 4] = o1;
}

// ---------------------------------------------------------------------------
// Aggregation, layer 4.  Warp per node; one 16B gather = all 4 heads.
// ---------------------------------------------------------------------------
__global__ void k_agg4(const float* __restrict__ bias) {
    int wid  = (blockIdx.x * blockDim.x + threadIdx.x) >> 5;
    int lane = threadIdx.x & 31;
    const int hm = lane & 3;
    float2 b = *(const float2*)&bias[2 * lane];

    gdep_sync();
    if (wid >= NNODES) return;
    const int d  = wid;
    const float adv_m = g_adst[d * 4 + hm];
    const int r0 = g_rowstart[d];
    const int r1 = g_rowstart[d + 1];
    const uint4* __restrict__ ftp = (const uint4*)g_ft4;

    float den[4] = {0.f, 0.f, 0.f, 0.f};
    float ax[4]  = {0.f, 0.f, 0.f, 0.f};
    float ay[4]  = {0.f, 0.f, 0.f, 0.f};
#pragma unroll 4
    for (int j = r0; j < r1; j++) {
        int s = g_col[j];
        float em = __expf(leaky02(g_asrc[s * 4 + hm] + adv_m));
        float ev0 = __shfl_sync(0xffffffff, em, 0, 4);
        float ev1 = __shfl_sync(0xffffffff, em, 1, 4);
        float ev2 = __shfl_sync(0xffffffff, em, 2, 4);
        float ev3 = __shfl_sync(0xffffffff, em, 3, 4);
        uint4 raw = __ldg(&ftp[s * 32 + lane]);
        float2 f0 = __half22float2(*(const __half2*)&raw.x);
        float2 f1 = __half22float2(*(const __half2*)&raw.y);
        float2 f2 = __half22float2(*(const __half2*)&raw.z);
        float2 f3 = __half22float2(*(const __half2*)&raw.w);
        den[0] += ev0; ax[0] += ev0 * f0.x; ay[0] += ev0 * f0.y;
        den[1] += ev1; ax[1] += ev1 * f1.x; ay[1] += ev1 * f1.y;
        den[2] += ev2; ax[2] += ev2 * f2.x; ay[2] += ev2 * f2.y;
        den[3] += ev3; ax[3] += ev3 * f3.x; ay[3] += ev3 * f3.y;
    }
    float v1 = 0.f, v2 = 0.f;
#pragma unroll
    for (int hh = 0; hh < 4; hh++) {
        float inv = 1.f / den[hh];
        v1 += ax[hh] * inv;
        v2 += ay[hh] * inv;
    }
    float2 o;
    o.x = eluf(0.25f * v1 + b.x);
    o.y = eluf(0.25f * v2 + b.y);
    *(float2*)&g_featA[d * 64 + 2 * lane] = o;
}

// ---------------------------------------------------------------------------
// Fused pool+head (8 blocks).  PDL prologue: binary search on flag (input).
// ---------------------------------------------------------------------------
__global__ void k_poolhead(const int* __restrict__ fidx, const int* __restrict__ flag,
                           int nf,
                           const int* __restrict__ dvi,
                           const float* __restrict__ Wp,
                           const float* __restrict__ Wt,
                           const float* __restrict__ Wo,
                           const float* __restrict__ bo,
                           float* __restrict__ out) {
    __shared__ float sred[4][64];
    __shared__ float sfp[64], stg[64], red[128];
    const int g = blockIdx.x;
    const int t = threadIdx.x;
    const int c   = t & 63;
    const int row = t >> 6;

    int lo, hi;
    {
        int a = 0, b = nf;
        while (a < b) { int m2 = (a + b) >> 1; if (flag[m2] < g) a = m2 + 1; else b = m2; }
        lo = a;
        a = lo; b = nf;
        while (a < b) { int m2 = (a + b) >> 1; if (flag[m2] < g + 1) a = m2 + 1; else b = m2; }
        hi = a;
    }
    int dv = dvi[g];

    gdep_sync();

    float acc = 0.f;
    for (int i = lo + row; i < hi; i += 4)
        acc += g_featA[fidx[i] * 64 + c];
    sred[row][c] = acc;
    __syncthreads();
    if (t < 64) {
        sfp[t] = sred[0][t] + sred[1][t] + sred[2][t] + sred[3][t];
        stg[t] = g_featA[dv * 64 + t];
    }
    __syncthreads();
    if (t < 128) {
        float a2 = 0.f;
        if (t < 64) {
#pragma unroll
            for (int k = 0; k < 64; k++) a2 += sfp[k] * Wp[k * 64 + t];
        } else {
            int cc = t - 64;
#pragma unroll
            for (int k = 0; k < 64; k++) a2 += stg[k] * Wt[k * 64 + cc];
        }
        red[t] = eluf(a2) * Wo[t];
    }
    __syncthreads();
    for (int s2 = 64; s2 > 0; s2 >>= 1) {
        if (t < s2) red[t] += red[t + s2];
        __syncthreads();
    }
    if (t == 0) out[g] = red[0] + bo[0];
}

// ---------------------------------------------------------------------------
// PDL launch helper
// ---------------------------------------------------------------------------
template <typename K, typename... Args>
static inline void launch_pdl(K kernel, int grid, int block, Args... args) {
    cudaLaunchConfig_t cfg = {};
    cfg.gridDim  = dim3(grid, 1, 1);
    cfg.blockDim = dim3(block, 1, 1);
    cfg.stream   = 0;
    cudaLaunchAttribute attr[1];
    attr[0].id = cudaLaunchAttributeProgrammaticStreamSerialization;
    attr[0].val.programmaticStreamSerializationAllowed = 1;
    cfg.attrs = attr;
    cfg.numAttrs = 1;
    cudaLaunchKernelEx(&cfg, kernel, args...);
}

// ---------------------------------------------------------------------------
extern "C" void kernel_launch(void* const* d_in, const int* in_sizes, int n_in,
                              void* d_out, int out_size) {
    const float* x     = (const float*)d_in[0];
    const int*   ei    = (const int*)  d_in[1];
    const int*   fidx  = (const int*)  d_in[2];
    const int*   flag  = (const int*)  d_in[3];
    const int*   dvi   = (const int*)  d_in[4];
    const float* W1    = (const float*)d_in[5];
    const float* as1   = (const float*)d_in[6];
    const float* ad1   = (const float*)d_in[7];
    const float* b1    = (const float*)d_in[8];
    const float* W2    = (const float*)d_in[9];
    const float* as2   = (const float*)d_in[10];
    const float* ad2   = (const float*)d_in[11];
    const float* b2    = (const float*)d_in[12];
    const float* W3    = (const float*)d_in[13];
    const float* as3   = (const float*)d_in[14];
    const float* ad3   = (const float*)d_in[15];
    const float* b3    = (const float*)d_in[16];
    const float* W4    = (const float*)d_in[17];
    const float* as4   = (const float*)d_in[18];
    const float* ad4   = (const float*)d_in[19];
    const float* b4    = (const float*)d_in[20];
    const float* Wp    = (const float*)d_in[21];
    const float* Wt    = (const float*)d_in[22];
    const float* Wo    = (const float*)d_in[23];
    const float* bo    = (const float*)d_in[24];
    float* out = (float*)d_out;

    const int nf  = in_sizes[2];                     // 8000
    const int AB8 = (NNODES / 4 * 32 + 255) / 256;   // 625
    const int AB4 = (NNODES * 32 + 255) / 256;       // 2500

    static cudaStream_t s2 = nullptr;
    static cudaEvent_t evFork = nullptr, evJoin = nullptr;
    if (s2 == nullptr) {
        cudaStreamCreateWithFlags(&s2, cudaStreamNonBlocking);
        cudaEventCreateWithFlags(&evFork, cudaEventDisableTiming);
        cudaEventCreateWithFlags(&evJoin, cudaEventDisableTiming);
    }

    // ---- Fork: CSR build on s2, transform1 on main ----
    cudaEventRecord(evFork, 0);
    cudaStreamWaitEvent(s2, evFork, 0);
    k_count<<<CSR_BLKS, 256, 0, s2>>>(ei);
    k_scan<<<1, SCAN_T, 0, s2>>>();
    k_fill<<<CSR_BLKS, 256, 0, s2>>>(ei);
    cudaEventRecord(evJoin, s2);

    k_transform64<16, false, false><<<1250, 256>>>(x, W1, as1, ad1);

    cudaStreamWaitEvent(0, evJoin, 0);

    // ---- Layer chain with PDL overlap ----
    k_agg8<false><<<AB8, 256>>>(b1);                             // plain (post-join)
    launch_pdl(k_transform64<64, true, true>, 1250, 256, (const float*)nullptr, W2, as2, ad2);
    launch_pdl(k_agg8<true>, AB8, 256, b2);
    launch_pdl(k_transform64<64, true, true>, 1250, 256, (const float*)nullptr, W3, as3, ad3);
    launch_pdl(k_agg8<true>, AB8, 256, b3);
    launch_pdl(k_transform4, 1250, 256, W4, as4, ad4);
    launch_pdl(k_agg4, AB4, 256, b4);
    launch_pdl(k_poolhead, NG, 256, fidx, flag, nf, dvi, Wp, Wt, Wo, bo, out);
}